// round 12
// baseline (speedup 1.0000x reference)
#include <cuda_runtime.h>
#include <cuda_bf16.h>
#include <cstdint>

#define NN 200000
#define PADK 200704      // 98*2048 padded rows (>= 1563*128)
#define NA 300
#define NAP 320
#define NF 128
#define NC 32

#define SLICE_K 2048
#define NSLICE 98
#define KT 32

// ---------------- device scratch (row-padded to PADK) ----------------
__device__ __nv_bfloat16 g_adj_hi[(size_t)PADK * NAP];
__device__ __nv_bfloat16 g_adj_lo[(size_t)PADK * NAP];
__device__ __nv_bfloat16 g_hh[(size_t)PADK * NF];
__device__ __nv_bfloat16 g_hl[(size_t)PADK * NF];
__device__ float g_U[384 * NF];
__device__ __nv_bfloat16 g_MT_hi[NF * NAP];
__device__ __nv_bfloat16 g_MT_lo[NF * NAP];
__device__ float g_rowsum[NN];
__device__ float g_colsum[384];

// ---------------- helpers ----------------
__device__ __forceinline__ uint32_t smem_u32(const void* p) {
    uint32_t a;
    asm("{ .reg .u64 t; cvta.to.shared.u64 t, %1; cvt.u32.u64 %0, t; }"
        : "=r"(a) : "l"(p));
    return a;
}
__device__ __forceinline__ void cpa(uint32_t dst, const void* src) {
    asm volatile("cp.async.cg.shared.global [%0], [%1], 16;"
                 :: "r"(dst), "l"(src) : "memory");
}
__device__ __forceinline__ void cpa_commit() {
    asm volatile("cp.async.commit_group;" ::: "memory");
}
template<int N> __device__ __forceinline__ void cpa_wait() {
    asm volatile("cp.async.wait_group %0;" :: "n"(N) : "memory");
}
__device__ __forceinline__ void ldm4(uint32_t* r, uint32_t a) {
    asm volatile("ldmatrix.sync.aligned.m8n8.x4.shared.b16 {%0,%1,%2,%3}, [%4];"
        : "=r"(r[0]), "=r"(r[1]), "=r"(r[2]), "=r"(r[3]) : "r"(a));
}
__device__ __forceinline__ void ldm4t(uint32_t* r, uint32_t a) {
    asm volatile("ldmatrix.sync.aligned.m8n8.x4.trans.shared.b16 {%0,%1,%2,%3}, [%4];"
        : "=r"(r[0]), "=r"(r[1]), "=r"(r[2]), "=r"(r[3]) : "r"(a));
}
__device__ __forceinline__ void mma16816(float* d, const uint32_t* a, const uint32_t* b) {
    asm volatile("mma.sync.aligned.m16n8k16.row.col.f32.bf16.bf16.f32 "
        "{%0,%1,%2,%3}, {%4,%5,%6,%7}, {%8,%9}, {%0,%1,%2,%3};"
        : "+f"(d[0]), "+f"(d[1]), "+f"(d[2]), "+f"(d[3])
        : "r"(a[0]), "r"(a[1]), "r"(a[2]), "r"(a[3]), "r"(b[0]), "r"(b[1]));
}

__device__ __forceinline__ void split1(float v, __nv_bfloat16& h, __nv_bfloat16& l) {
    h = __float2bfloat16(v);
    l = __float2bfloat16(v - __bfloat162float(h));
}
__device__ __forceinline__ void split2(float v0, float v1, uint32_t& hi, uint32_t& lo) {
    __nv_bfloat16 h0, l0, h1, l1;
    split1(v0, h0, l0); split1(v1, h1, l1);
    __nv_bfloat162 hp = __halves2bfloat162(h0, h1);
    __nv_bfloat162 lp = __halves2bfloat162(l0, l1);
    hi = *reinterpret_cast<uint32_t*>(&hp);
    lo = *reinterpret_cast<uint32_t*>(&lp);
}

// ---------------------------------------------------------------------------
#define PADR (PADK - NN)   // 704
__global__ void init_kernel() {
    int i = blockIdx.x * blockDim.x + threadIdx.x;
    if (i < 384 * NF) g_U[i] = 0.f;
    if (i < 384) g_colsum[i] = 0.f;
    if (i < NF * NAP / 2) {
        reinterpret_cast<uint32_t*>(g_MT_hi)[i] = 0u;
        reinterpret_cast<uint32_t*>(g_MT_lo)[i] = 0u;
    }
    if (i < PADR * NAP / 2) {
        reinterpret_cast<uint32_t*>(g_adj_hi + (size_t)NN * NAP)[i] = 0u;
        reinterpret_cast<uint32_t*>(g_adj_lo + (size_t)NN * NAP)[i] = 0u;
    }
    if (i < PADR * NF / 2) {
        reinterpret_cast<uint32_t*>(g_hh + (size_t)NN * NF)[i] = 0u;
        reinterpret_cast<uint32_t*>(g_hl + (size_t)NN * NF)[i] = 0u;
    }
}

// ---------------------------------------------------------------------------
// adj -> bf16 hi/lo (padded 320 cols) + rowsum + colsum in one pass
// ---------------------------------------------------------------------------
__device__ __forceinline__ void w4(__nv_bfloat16* ph, __nv_bfloat16* pl, float4 v) {
    uint32_t hA, lA, hB, lB;
    split2(v.x, v.y, hA, lA);
    split2(v.z, v.w, hB, lB);
    *reinterpret_cast<uint2*>(ph) = make_uint2(hA, hB);
    *reinterpret_cast<uint2*>(pl) = make_uint2(lA, lB);
}

#define CONV_ROWS 250
__global__ void __launch_bounds__(256) conv_adj_kernel(const float* __restrict__ adj) {
    const int tx = threadIdx.x & 31;
    const int ty = threadIdx.x >> 5;
    const int r0 = blockIdx.x * CONV_ROWS;
    const int r1 = min(r0 + CONV_ROWS, NN);

    float ca[12];
#pragma unroll
    for (int j = 0; j < 12; j++) ca[j] = 0.f;

    for (int r = r0 + ty; r < r1; r += 8) {
        const float4* row4 = (const float4*)(adj + (size_t)r * NA);
        float4 v0 = row4[tx];
        float4 v1 = row4[32 + tx];
        float4 v2 = (tx < 11) ? row4[64 + tx] : make_float4(0.f, 0.f, 0.f, 0.f);
        ca[0] += v0.x; ca[1] += v0.y; ca[2]  += v0.z; ca[3]  += v0.w;
        ca[4] += v1.x; ca[5] += v1.y; ca[6]  += v1.z; ca[7]  += v1.w;
        ca[8] += v2.x; ca[9] += v2.y; ca[10] += v2.z; ca[11] += v2.w;
        float rp = v0.x + v0.y + v0.z + v0.w
                 + v1.x + v1.y + v1.z + v1.w
                 + v2.x + v2.y + v2.z + v2.w;
#pragma unroll
        for (int o = 16; o > 0; o >>= 1)
            rp += __shfl_down_sync(0xffffffffu, rp, o);
        if (tx == 0) g_rowsum[r] = rp;

        __nv_bfloat16* oh = g_adj_hi + (size_t)r * NAP;
        __nv_bfloat16* ol = g_adj_lo + (size_t)r * NAP;
        w4(oh + 4 * tx,        ol + 4 * tx,        v0);
        w4(oh + 4 * (32 + tx), ol + 4 * (32 + tx), v1);
        if (tx < 16) w4(oh + 4 * (64 + tx), ol + 4 * (64 + tx), v2);
    }

    __shared__ float sc[8][12][32];
#pragma unroll
    for (int j = 0; j < 12; j++) sc[ty][j][tx] = ca[j];
    __syncthreads();
    if (ty == 0) {
#pragma unroll
        for (int j = 0; j < 12; j++) {
            float s = 0.f;
#pragma unroll
            for (int t = 0; t < 8; t++) s += sc[t][j][tx];
            int col = (j >> 2) * 128 + tx * 4 + (j & 3);
            if (col < NA) atomicAdd(&g_colsum[col], s);
        }
    }
}

// ---------------------------------------------------------------------------
__global__ void conv_x_kernel(const float* __restrict__ x) {
    size_t i = (size_t)blockIdx.x * blockDim.x + threadIdx.x;
    if (i < (size_t)NN * NF / 4) {
        float4 v = ((const float4*)x)[i];
        uint32_t hA, lA, hB, lB;
        split2(v.x, v.y, hA, lA);
        split2(v.z, v.w, hB, lB);
        *reinterpret_cast<uint2*>(g_hh + 4 * i) = make_uint2(hA, hB);
        *reinterpret_cast<uint2*>(g_hl + 4 * i) = make_uint2(lA, lB);
    }
}

// ---------------------------------------------------------------------------
// upass: U[a][d] += sum_k adj[k][a]*h[k][d].
// grid(3, 98): anchor chunks {128, 128, 64}. 256 thr, 8 warps.
// 3-stage cp.async pipeline (2 load-groups in flight during compute).
// ---------------------------------------------------------------------------
template<int AW>
__device__ __forceinline__ void upass_body(uint32_t sb, int a0, size_t k0, int tid) {
    constexpr int PA  = AW * 2 + 16;      // 272 or 144
    constexpr int PB  = 272;
    constexpr int SAB = KT * PA;
    constexpr int SBB = KT * PB;
    constexpr int STG = 2 * SAB + 2 * SBB;
    constexpr int WN  = (AW == 128) ? 2 : 4;
    constexpr int ND  = 128 / WN;
    constexpr int N8  = ND / 8;
    constexpr int NBP = ND / 16;
    constexpr int ACH = KT * (AW / 8);

    const int wid = tid >> 5, L = tid & 31;
    const int warp_m = wid / WN, warp_n = wid % WN;

    float acc[2][N8][4];
#pragma unroll
    for (int i = 0; i < 2; i++)
#pragma unroll
        for (int j = 0; j < N8; j++)
#pragma unroll
            for (int q = 0; q < 4; q++) acc[i][j][q] = 0.f;

    auto load = [&](uint32_t base, size_t kt) {
#pragma unroll
        for (int it = 0; it < 2 * ACH / 256; it++) {
            int idx = tid + it * 256;
            int buf = idx / ACH, rem = idx % ACH;
            int row = rem / (AW / 8), c = rem % (AW / 8);
            const __nv_bfloat16* src = (buf ? g_adj_lo : g_adj_hi)
                                       + (kt + row) * NAP + a0 + c * 8;
            cpa(base + buf * SAB + row * PA + c * 16, src);
        }
#pragma unroll
        for (int it = 0; it < 4; it++) {
            int idx = tid + it * 256;
            int buf = idx >> 9, rem = idx & 511;
            int row = rem >> 4, c = rem & 15;
            const __nv_bfloat16* src = (buf ? g_hl : g_hh) + (kt + row) * NF + c * 8;
            cpa(base + 2 * SAB + buf * SBB + row * PB + c * 16, src);
        }
    };

    auto compute = [&](uint32_t st) {
        const uint32_t Ah = st, Al = st + SAB;
        const uint32_t Bh = st + 2 * SAB, Bl = Bh + SBB;
#pragma unroll
        for (int ks = 0; ks < 2; ks++) {
            const uint32_t aoff = (uint32_t)(ks * 16 + ((L >> 4) & 1) * 8 + (L & 7)) * PA
                                + ((L >> 3) & 1) * 16;
            uint32_t AF[2][2][4];
#pragma unroll
            for (int mb = 0; mb < 2; mb++) {
                uint32_t c2 = (uint32_t)(warp_m * 32 + mb * 16) * 2;
                ldm4t(AF[0][mb], Ah + aoff + c2);
                ldm4t(AF[1][mb], Al + aoff + c2);
            }
            const uint32_t boff = (uint32_t)(ks * 16 + ((L >> 3) & 1) * 8 + (L & 7)) * PB
                                + ((L >> 4) & 1) * 16;
#pragma unroll
            for (int nb = 0; nb < NBP; nb++) {
                uint32_t BH[4], BL[4];
                uint32_t c2 = (uint32_t)(warp_n * ND + nb * 16) * 2;
                ldm4t(BH, Bh + boff + c2);
                ldm4t(BL, Bl + boff + c2);
#pragma unroll
                for (int mb = 0; mb < 2; mb++)
#pragma unroll
                    for (int jj = 0; jj < 2; jj++) {
                        mma16816(acc[mb][nb * 2 + jj], AF[0][mb], &BH[jj * 2]);
                        mma16816(acc[mb][nb * 2 + jj], AF[0][mb], &BL[jj * 2]);
                        mma16816(acc[mb][nb * 2 + jj], AF[1][mb], &BH[jj * 2]);
                    }
            }
        }
    };

    const int T = SLICE_K / KT;  // 64
    load(sb + 0 * STG, k0);            cpa_commit();
    load(sb + 1 * STG, k0 + KT);       cpa_commit();

    int cur = 0, nxt = 2;
    for (int t = 0; t < T - 1; t++) {
        cpa_wait<1>();          // tile t complete; t+1 may still be in flight
        __syncthreads();        // all warps done with buffer `nxt` (used at t-1)
        if (t + 2 < T) {
            load(sb + nxt * STG, k0 + (size_t)(t + 2) * KT);
            cpa_commit();
        }
        compute(sb + cur * STG);
        cur = (cur == 2) ? 0 : cur + 1;
        nxt = (nxt == 2) ? 0 : nxt + 1;
    }
    cpa_wait<0>();
    __syncthreads();
    compute(sb + cur * STG);

#pragma unroll
    for (int mb = 0; mb < 2; mb++) {
        int a = a0 + warp_m * 32 + mb * 16 + (L >> 2);
#pragma unroll
        for (int j = 0; j < N8; j++) {
            int d = warp_n * ND + j * 8 + (L & 3) * 2;
            if (a < NA) {
                atomicAdd(&g_U[a * NF + d],     acc[mb][j][0]);
                atomicAdd(&g_U[a * NF + d + 1], acc[mb][j][1]);
            }
            if (a + 8 < NA) {
                atomicAdd(&g_U[(a + 8) * NF + d],     acc[mb][j][2]);
                atomicAdd(&g_U[(a + 8) * NF + d + 1], acc[mb][j][3]);
            }
        }
    }
}

#define U_STG128 (2 * (KT * 272) + 2 * (KT * 272))   // 34816
__global__ void __launch_bounds__(256, 2) upass_kernel() {
    extern __shared__ char smem[];
    const uint32_t sb = smem_u32(smem);
    const size_t k0 = (size_t)blockIdx.y * SLICE_K;
    if (blockIdx.x < 2)
        upass_body<128>(sb, blockIdx.x * 128, k0, threadIdx.x);
    else
        upass_body<64>(sb, 256, k0, threadIdx.x);
}

// ---------------------------------------------------------------------------
// mkM: M^T[d][a] = (U[a] @ W)[d] / clamp(colsum[a]) as bf16 hi/lo; zero U row.
// ---------------------------------------------------------------------------
template<int DOUT>
__global__ void mkM_kernel(const float* __restrict__ W) {
    __shared__ float u_s[NF];
    const int a = blockIdx.x;
    const int d = threadIdx.x;
    u_s[d] = g_U[a * NF + d];
    __syncthreads();
    g_U[a * NF + d] = 0.f;
    if (d < DOUT) {
        float cinv = 1.f / fmaxf(g_colsum[a], 1e-12f);
        float acc = 0.f;
#pragma unroll 8
        for (int k = 0; k < NF; k++)
            acc += u_s[k] * W[k * DOUT + d];
        __nv_bfloat16 hb, lb;
        split1(acc * cinv, hb, lb);
        g_MT_hi[d * NAP + a] = hb;
        g_MT_lo[d * NAP + a] = lb;
    }
}

// ---------------------------------------------------------------------------
// ppass: C[n][d] = sum_a adj[n][a]*M[a][d]; 512 thr, 16 warps.
// 3-stage cp.async pipeline.
// ---------------------------------------------------------------------------
template<int NOUT, bool FINAL>
__global__ void __launch_bounds__(512) ppass_kernel(float* __restrict__ out) {
    constexpr int WM = (NOUT == 128) ? 4 : 8;
    constexpr int WN = 16 / WM;
    constexpr int MT = 128 / WM;
    constexpr int NT = NOUT / WN;
    constexpr int MB = MT / 16;
    constexpr int N8 = NT / 8;
    constexpr int NBP = NT / 16;
    constexpr int P = 80;
    constexpr int SA = 128 * P;
    constexpr int SB = NOUT * P;
    constexpr int STG = 2 * SA + 2 * SB;
    constexpr int BCH = NOUT * 8;

    extern __shared__ char smem[];
    const uint32_t sb = smem_u32(smem);
    const int tid = threadIdx.x, wid = tid >> 5, L = tid & 31;
    const int warp_m = wid / WN, warp_n = wid % WN;
    const size_t n0 = (size_t)blockIdx.x * 128;

    float acc[MB][N8][4];
#pragma unroll
    for (int i = 0; i < MB; i++)
#pragma unroll
        for (int j = 0; j < N8; j++)
#pragma unroll
            for (int q = 0; q < 4; q++) acc[i][j][q] = 0.f;

    auto load_tile = [&](int t, int stage) {
        uint32_t base = sb + stage * STG;
#pragma unroll
        for (int it = 0; it < 2; it++) {
            int idx = tid + it * 512;
            int buf = idx >> 9, rem = idx & 511;
            int row = rem >> 2, c = rem & 3;
            const __nv_bfloat16* src = (buf ? g_adj_lo : g_adj_hi)
                                       + (n0 + row) * NAP + t * KT + c * 8;
            cpa(base + buf * SA + row * P + c * 16, src);
        }
        if (tid < BCH) {
            int buf = tid / (BCH / 2), rem = tid % (BCH / 2);
            int row = rem >> 2, c = rem & 3;
            const __nv_bfloat16* src = (buf ? g_MT_lo : g_MT_hi) + row * NAP + t * KT + c * 8;
            cpa(base + 2 * SA + buf * SB + row * P + c * 16, src);
        }
        if (BCH > 512 && tid + 512 < BCH) {
            int idx = tid + 512;
            int buf = idx / (BCH / 2), rem = idx % (BCH / 2);
            int row = rem >> 2, c = rem & 3;
            const __nv_bfloat16* src = (buf ? g_MT_lo : g_MT_hi) + row * NAP + t * KT + c * 8;
            cpa(base + 2 * SA + buf * SB + row * P + c * 16, src);
        }
    };

    auto compute = [&](uint32_t st) {
        const uint32_t Ah = st, Al = st + SA;
        const uint32_t Bh = st + 2 * SA, Bl = Bh + SB;
#pragma unroll
        for (int ks = 0; ks < 2; ks++) {
            const uint32_t aoff = (uint32_t)(((L >> 3) & 1) * 8 + (L & 7)) * P
                                + ks * 32 + ((L >> 4) & 1) * 16;
            uint32_t AF[2][MB][4];
#pragma unroll
            for (int mb = 0; mb < MB; mb++) {
                uint32_t ro = (uint32_t)(warp_m * MT + mb * 16) * P;
                ldm4(AF[0][mb], Ah + ro + aoff);
                ldm4(AF[1][mb], Al + ro + aoff);
            }
            const uint32_t boff = (uint32_t)(((L >> 4) & 1) * 8 + (L & 7)) * P
                                + ks * 32 + ((L >> 3) & 1) * 16;
            uint32_t BF[2][NBP][4];
#pragma unroll
            for (int nb = 0; nb < NBP; nb++) {
                uint32_t ro = (uint32_t)(warp_n * NT + nb * 16) * P;
                ldm4(BF[0][nb], Bh + ro + boff);
                ldm4(BF[1][nb], Bl + ro + boff);
            }
#pragma unroll
            for (int mb = 0; mb < MB; mb++)
#pragma unroll
                for (int j = 0; j < N8; j++) {
                    const uint32_t* bh = &BF[0][j >> 1][(j & 1) * 2];
                    const uint32_t* bl = &BF[1][j >> 1][(j & 1) * 2];
                    mma16816(acc[mb][j], AF[0][mb], bh);
                    mma16816(acc[mb][j], AF[0][mb], bl);
                    mma16816(acc[mb][j], AF[1][mb], bh);
                }
        }
    };

    const int T = NAP / KT;  // 10
    load_tile(0, 0); cpa_commit();
    load_tile(1, 1); cpa_commit();

    int cur = 0, nxt = 2;
    for (int t = 0; t < T - 1; t++) {
        cpa_wait<1>();
        __syncthreads();
        if (t + 2 < T) {
            load_tile(t + 2, nxt);
            cpa_commit();
        }
        compute(sb + cur * STG);
        cur = (cur == 2) ? 0 : cur + 1;
        nxt = (nxt == 2) ? 0 : nxt + 1;
    }
    cpa_wait<0>();
    __syncthreads();
    compute(sb + cur * STG);

    // epilogue
#pragma unroll
    for (int mb = 0; mb < MB; mb++) {
        size_t r0 = n0 + warp_m * MT + mb * 16 + (L >> 2);
        size_t r1 = r0 + 8;
        float ri0 = (r0 < NN) ? 1.f / fmaxf(g_rowsum[r0], 1e-12f) : 0.f;
        float ri1 = (r1 < NN) ? 1.f / fmaxf(g_rowsum[r1], 1e-12f) : 0.f;
#pragma unroll
        for (int j = 0; j < N8; j++) {
            int d = warp_n * NT + j * 8 + (L & 3) * 2;
            if (FINAL) {
                if (r0 < NN) {
                    float2 o = make_float2(acc[mb][j][0] * ri0, acc[mb][j][1] * ri0);
                    *(float2*)(out + r0 * NC + d) = o;
                }
                if (r1 < NN) {
                    float2 o = make_float2(acc[mb][j][2] * ri1, acc[mb][j][3] * ri1);
                    *(float2*)(out + r1 * NC + d) = o;
                }
            } else {
                if (r0 < NN) {
                    float v0 = fmaxf(acc[mb][j][0] * ri0, 0.f);
                    float v1 = fmaxf(acc[mb][j][1] * ri0, 0.f);
                    uint32_t hi, lo;
                    split2(v0, v1, hi, lo);
                    *(uint32_t*)(g_hh + r0 * NF + d) = hi;
                    *(uint32_t*)(g_hl + r0 * NF + d) = lo;
                }
                if (r1 < NN) {
                    float v0 = fmaxf(acc[mb][j][2] * ri1, 0.f);
                    float v1 = fmaxf(acc[mb][j][3] * ri1, 0.f);
                    uint32_t hi, lo;
                    split2(v0, v1, hi, lo);
                    *(uint32_t*)(g_hh + r1 * NF + d) = hi;
                    *(uint32_t*)(g_hl + r1 * NF + d) = lo;
                }
            }
        }
    }
}

// ---------------------------------------------------------------------------
extern "C" void kernel_launch(void* const* d_in, const int* in_sizes, int n_in,
                              void* d_out, int out_size) {
    const float* x   = (const float*)d_in[0];
    const float* adj = (const float*)d_in[1];
    const float* W1  = (const float*)d_in[2];
    const float* W2  = (const float*)d_in[3];
    const float* W3  = (const float*)d_in[4];
    float* out = (float*)d_out;

    cudaFuncSetAttribute(upass_kernel,
                         cudaFuncAttributeMaxDynamicSharedMemorySize, 3 * U_STG128);
    cudaFuncSetAttribute(ppass_kernel<128, false>,
                         cudaFuncAttributeMaxDynamicSharedMemorySize, 3 * 40960);
    cudaFuncSetAttribute(ppass_kernel<32, true>,
                         cudaFuncAttributeMaxDynamicSharedMemorySize, 3 * 25600);

    init_kernel<<<440, 256>>>();
    conv_adj_kernel<<<800, 256>>>(adj);
    conv_x_kernel<<<25600, 256>>>(x);

    dim3 ugrid(3, NSLICE);

    upass_kernel<<<ugrid, 256, 3 * U_STG128>>>();
    mkM_kernel<128><<<NA, 128>>>(W1);
    ppass_kernel<128, false><<<1563, 512, 3 * 40960>>>(nullptr);

    upass_kernel<<<ugrid, 256, 3 * U_STG128>>>();
    mkM_kernel<128><<<NA, 128>>>(W2);
    ppass_kernel<128, false><<<1563, 512, 3 * 40960>>>(nullptr);

    upass_kernel<<<ugrid, 256, 3 * U_STG128>>>();
    mkM_kernel<32><<<NA, 128>>>(W3);
    ppass_kernel<32, true><<<1563, 512, 3 * 25600>>>(out);
}

// round 13
// speedup vs baseline: 1.0261x; 1.0261x over previous
#include <cuda_runtime.h>
#include <cuda_bf16.h>
#include <cstdint>

#define NN 200000
#define PADK 200704
#define NA 300
#define NAP 320
#define NF 128
#define NC 32

#define SLICE_K 2048
#define NSLICE 98
#define KT 32

// ---------------- device scratch (row-padded to PADK) ----------------
__device__ __nv_bfloat16 g_adj_hi[(size_t)PADK * NAP];
__device__ __nv_bfloat16 g_adj_lo[(size_t)PADK * NAP];
__device__ __nv_bfloat16 g_hh[(size_t)PADK * NF];
__device__ __nv_bfloat16 g_hl[(size_t)PADK * NF];
__device__ float g_U[384 * NF];
__device__ __nv_bfloat16 g_MT_hi[NF * NAP];
__device__ __nv_bfloat16 g_MT_lo[NF * NAP];
__device__ float g_rowsum[NN];
__device__ float g_colsum[384];

// ---------------- helpers ----------------
__device__ __forceinline__ uint32_t smem_u32(const void* p) {
    uint32_t a;
    asm("{ .reg .u64 t; cvta.to.shared.u64 t, %1; cvt.u32.u64 %0, t; }"
        : "=r"(a) : "l"(p));
    return a;
}
__device__ __forceinline__ void cpa(uint32_t dst, const void* src) {
    asm volatile("cp.async.cg.shared.global [%0], [%1], 16;"
                 :: "r"(dst), "l"(src) : "memory");
}
__device__ __forceinline__ void cpa_commit() {
    asm volatile("cp.async.commit_group;" ::: "memory");
}
template<int N> __device__ __forceinline__ void cpa_wait() {
    asm volatile("cp.async.wait_group %0;" :: "n"(N) : "memory");
}
__device__ __forceinline__ void ldm4(uint32_t* r, uint32_t a) {
    asm volatile("ldmatrix.sync.aligned.m8n8.x4.shared.b16 {%0,%1,%2,%3}, [%4];"
        : "=r"(r[0]), "=r"(r[1]), "=r"(r[2]), "=r"(r[3]) : "r"(a));
}
__device__ __forceinline__ void ldm4t(uint32_t* r, uint32_t a) {
    asm volatile("ldmatrix.sync.aligned.m8n8.x4.trans.shared.b16 {%0,%1,%2,%3}, [%4];"
        : "=r"(r[0]), "=r"(r[1]), "=r"(r[2]), "=r"(r[3]) : "r"(a));
}
__device__ __forceinline__ void mma16816(float* d, const uint32_t* a, const uint32_t* b) {
    asm volatile("mma.sync.aligned.m16n8k16.row.col.f32.bf16.bf16.f32 "
        "{%0,%1,%2,%3}, {%4,%5,%6,%7}, {%8,%9}, {%0,%1,%2,%3};"
        : "+f"(d[0]), "+f"(d[1]), "+f"(d[2]), "+f"(d[3])
        : "r"(a[0]), "r"(a[1]), "r"(a[2]), "r"(a[3]), "r"(b[0]), "r"(b[1]));
}

__device__ __forceinline__ void split1(float v, __nv_bfloat16& h, __nv_bfloat16& l) {
    h = __float2bfloat16(v);
    l = __float2bfloat16(v - __bfloat162float(h));
}
__device__ __forceinline__ void split2(float v0, float v1, uint32_t& hi, uint32_t& lo) {
    __nv_bfloat16 h0, l0, h1, l1;
    split1(v0, h0, l0); split1(v1, h1, l1);
    __nv_bfloat162 hp = __halves2bfloat162(h0, h1);
    __nv_bfloat162 lp = __halves2bfloat162(l0, l1);
    hi = *reinterpret_cast<uint32_t*>(&hp);
    lo = *reinterpret_cast<uint32_t*>(&lp);
}

// ---------------------------------------------------------------------------
#define PADR (PADK - NN)
__global__ void init_kernel() {
    int i = blockIdx.x * blockDim.x + threadIdx.x;
    if (i < 384 * NF) g_U[i] = 0.f;
    if (i < 384) g_colsum[i] = 0.f;
    if (i < NF * NAP / 2) {
        reinterpret_cast<uint32_t*>(g_MT_hi)[i] = 0u;
        reinterpret_cast<uint32_t*>(g_MT_lo)[i] = 0u;
    }
    if (i < PADR * NAP / 2) {
        reinterpret_cast<uint32_t*>(g_adj_hi + (size_t)NN * NAP)[i] = 0u;
        reinterpret_cast<uint32_t*>(g_adj_lo + (size_t)NN * NAP)[i] = 0u;
    }
    if (i < PADR * NF / 2) {
        reinterpret_cast<uint32_t*>(g_hh + (size_t)NN * NF)[i] = 0u;
        reinterpret_cast<uint32_t*>(g_hl + (size_t)NN * NF)[i] = 0u;
    }
}

// ---------------------------------------------------------------------------
__device__ __forceinline__ void w4(__nv_bfloat16* ph, __nv_bfloat16* pl, float4 v) {
    uint32_t hA, lA, hB, lB;
    split2(v.x, v.y, hA, lA);
    split2(v.z, v.w, hB, lB);
    *reinterpret_cast<uint2*>(ph) = make_uint2(hA, hB);
    *reinterpret_cast<uint2*>(pl) = make_uint2(lA, lB);
}

#define CONV_ROWS 250
__global__ void __launch_bounds__(256) conv_adj_kernel(const float* __restrict__ adj) {
    const int tx = threadIdx.x & 31;
    const int ty = threadIdx.x >> 5;
    const int r0 = blockIdx.x * CONV_ROWS;
    const int r1 = min(r0 + CONV_ROWS, NN);

    float ca[12];
#pragma unroll
    for (int j = 0; j < 12; j++) ca[j] = 0.f;

    for (int r = r0 + ty; r < r1; r += 8) {
        const float4* row4 = (const float4*)(adj + (size_t)r * NA);
        float4 v0 = row4[tx];
        float4 v1 = row4[32 + tx];
        float4 v2 = (tx < 11) ? row4[64 + tx] : make_float4(0.f, 0.f, 0.f, 0.f);
        ca[0] += v0.x; ca[1] += v0.y; ca[2]  += v0.z; ca[3]  += v0.w;
        ca[4] += v1.x; ca[5] += v1.y; ca[6]  += v1.z; ca[7]  += v1.w;
        ca[8] += v2.x; ca[9] += v2.y; ca[10] += v2.z; ca[11] += v2.w;
        float rp = v0.x + v0.y + v0.z + v0.w
                 + v1.x + v1.y + v1.z + v1.w
                 + v2.x + v2.y + v2.z + v2.w;
#pragma unroll
        for (int o = 16; o > 0; o >>= 1)
            rp += __shfl_down_sync(0xffffffffu, rp, o);
        if (tx == 0) g_rowsum[r] = rp;

        __nv_bfloat16* oh = g_adj_hi + (size_t)r * NAP;
        __nv_bfloat16* ol = g_adj_lo + (size_t)r * NAP;
        w4(oh + 4 * tx,        ol + 4 * tx,        v0);
        w4(oh + 4 * (32 + tx), ol + 4 * (32 + tx), v1);
        if (tx < 16) w4(oh + 4 * (64 + tx), ol + 4 * (64 + tx), v2);
    }

    __shared__ float sc[8][12][32];
#pragma unroll
    for (int j = 0; j < 12; j++) sc[ty][j][tx] = ca[j];
    __syncthreads();
    if (ty == 0) {
#pragma unroll
        for (int j = 0; j < 12; j++) {
            float s = 0.f;
#pragma unroll
            for (int t = 0; t < 8; t++) s += sc[t][j][tx];
            int col = (j >> 2) * 128 + tx * 4 + (j & 3);
            if (col < NA) atomicAdd(&g_colsum[col], s);
        }
    }
}

// ---------------------------------------------------------------------------
__global__ void conv_x_kernel(const float* __restrict__ x) {
    size_t i = (size_t)blockIdx.x * blockDim.x + threadIdx.x;
    if (i < (size_t)NN * NF / 4) {
        float4 v = ((const float4*)x)[i];
        uint32_t hA, lA, hB, lB;
        split2(v.x, v.y, hA, lA);
        split2(v.z, v.w, hB, lB);
        *reinterpret_cast<uint2*>(g_hh + 4 * i) = make_uint2(hA, hB);
        *reinterpret_cast<uint2*>(g_hl + 4 * i) = make_uint2(lA, lB);
    }
}

// ---------------------------------------------------------------------------
// upass: U[a][d] += sum_k adj[k][a]*h[k][d].  grid(3, 98): chunks {128,128,64}.
// 256 thr, 2-stage cp.async pipeline (R11 config — best measured).
// ---------------------------------------------------------------------------
template<int AW>
__device__ __forceinline__ void upass_body(uint32_t sb, int a0, size_t k0, int tid) {
    constexpr int PA  = AW * 2 + 16;
    constexpr int PB  = 272;
    constexpr int SAB = KT * PA;
    constexpr int SBB = KT * PB;
    constexpr int STG = 2 * SAB + 2 * SBB;
    constexpr int WN  = (AW == 128) ? 2 : 4;
    constexpr int ND  = 128 / WN;
    constexpr int N8  = ND / 8;
    constexpr int NBP = ND / 16;
    constexpr int ACH = KT * (AW / 8);

    const int wid = tid >> 5, L = tid & 31;
    const int warp_m = wid / WN, warp_n = wid % WN;

    float acc[2][N8][4];
#pragma unroll
    for (int i = 0; i < 2; i++)
#pragma unroll
        for (int j = 0; j < N8; j++)
#pragma unroll
            for (int q = 0; q < 4; q++) acc[i][j][q] = 0.f;

    auto load = [&](uint32_t base, size_t kt) {
#pragma unroll
        for (int it = 0; it < 2 * ACH / 256; it++) {
            int idx = tid + it * 256;
            int buf = idx / ACH, rem = idx % ACH;
            int row = rem / (AW / 8), c = rem % (AW / 8);
            const __nv_bfloat16* src = (buf ? g_adj_lo : g_adj_hi)
                                       + (kt + row) * NAP + a0 + c * 8;
            cpa(base + buf * SAB + row * PA + c * 16, src);
        }
#pragma unroll
        for (int it = 0; it < 4; it++) {
            int idx = tid + it * 256;
            int buf = idx >> 9, rem = idx & 511;
            int row = rem >> 4, c = rem & 15;
            const __nv_bfloat16* src = (buf ? g_hl : g_hh) + (kt + row) * NF + c * 8;
            cpa(base + 2 * SAB + buf * SBB + row * PB + c * 16, src);
        }
    };

    load(sb, k0);
    cpa_commit();

    const int T = SLICE_K / KT;  // 64
    for (int t = 0; t < T; t++) {
        cpa_wait<0>();
        __syncthreads();
        if (t + 1 < T) {
            load(sb + ((t + 1) & 1) * STG, k0 + (size_t)(t + 1) * KT);
            cpa_commit();
        }
        const uint32_t st = sb + (t & 1) * STG;
        const uint32_t Ah = st, Al = st + SAB;
        const uint32_t Bh = st + 2 * SAB, Bl = Bh + SBB;

#pragma unroll
        for (int ks = 0; ks < 2; ks++) {
            const uint32_t aoff = (uint32_t)(ks * 16 + ((L >> 4) & 1) * 8 + (L & 7)) * PA
                                + ((L >> 3) & 1) * 16;
            uint32_t AF[2][2][4];
#pragma unroll
            for (int mb = 0; mb < 2; mb++) {
                uint32_t c2 = (uint32_t)(warp_m * 32 + mb * 16) * 2;
                ldm4t(AF[0][mb], Ah + aoff + c2);
                ldm4t(AF[1][mb], Al + aoff + c2);
            }
            const uint32_t boff = (uint32_t)(ks * 16 + ((L >> 3) & 1) * 8 + (L & 7)) * PB
                                + ((L >> 4) & 1) * 16;
#pragma unroll
            for (int nb = 0; nb < NBP; nb++) {
                uint32_t BH[4], BL[4];
                uint32_t c2 = (uint32_t)(warp_n * ND + nb * 16) * 2;
                ldm4t(BH, Bh + boff + c2);
                ldm4t(BL, Bl + boff + c2);
#pragma unroll
                for (int mb = 0; mb < 2; mb++)
#pragma unroll
                    for (int jj = 0; jj < 2; jj++) {
                        mma16816(acc[mb][nb * 2 + jj], AF[0][mb], &BH[jj * 2]);
                        mma16816(acc[mb][nb * 2 + jj], AF[0][mb], &BL[jj * 2]);
                        mma16816(acc[mb][nb * 2 + jj], AF[1][mb], &BH[jj * 2]);
                    }
            }
        }
    }

#pragma unroll
    for (int mb = 0; mb < 2; mb++) {
        int a = a0 + warp_m * 32 + mb * 16 + (L >> 2);
#pragma unroll
        for (int j = 0; j < N8; j++) {
            int d = warp_n * ND + j * 8 + (L & 3) * 2;
            if (a < NA) {
                atomicAdd(&g_U[a * NF + d],     acc[mb][j][0]);
                atomicAdd(&g_U[a * NF + d + 1], acc[mb][j][1]);
            }
            if (a + 8 < NA) {
                atomicAdd(&g_U[(a + 8) * NF + d],     acc[mb][j][2]);
                atomicAdd(&g_U[(a + 8) * NF + d + 1], acc[mb][j][3]);
            }
        }
    }
}

#define U_STG128 (2 * (KT * 272) + 2 * (KT * 272))   // 34816
__global__ void __launch_bounds__(256, 2) upass_kernel() {
    extern __shared__ char smem[];
    const uint32_t sb = smem_u32(smem);
    const size_t k0 = (size_t)blockIdx.y * SLICE_K;
    if (blockIdx.x < 2)
        upass_body<128>(sb, blockIdx.x * 128, k0, threadIdx.x);
    else
        upass_body<64>(sb, 256, k0, threadIdx.x);
}

// ---------------------------------------------------------------------------
// mkM: two anchors per CTA (256 thr). M^T = (U@W)/clamp(colsum) bf16 hi/lo.
// ---------------------------------------------------------------------------
template<int DOUT>
__global__ void mkM_kernel(const float* __restrict__ W) {
    __shared__ float u_s[2][NF];
    const int half = threadIdx.x >> 7;         // 0 or 1
    const int d = threadIdx.x & 127;
    const int a = blockIdx.x * 2 + half;
    u_s[half][d] = g_U[a * NF + d];
    __syncthreads();
    g_U[a * NF + d] = 0.f;
    if (d < DOUT) {
        float cinv = 1.f / fmaxf(g_colsum[a], 1e-12f);
        float acc = 0.f;
#pragma unroll 8
        for (int k = 0; k < NF; k++)
            acc += u_s[half][k] * W[k * DOUT + d];
        __nv_bfloat16 hb, lb;
        split1(acc * cinv, hb, lb);
        g_MT_hi[d * NAP + a] = hb;
        g_MT_lo[d * NAP + a] = lb;
    }
}

// ---------------------------------------------------------------------------
// ppass: C[n][d] = sum_a adj[n][a]*M[a][d]; 512 thr, 2-stage pipeline.
// Epilogue stages results in smem, then fully-coalesced 16B global stores.
// ---------------------------------------------------------------------------
template<int NOUT, bool FINAL>
__global__ void __launch_bounds__(512) ppass_kernel(float* __restrict__ out) {
    constexpr int WM = (NOUT == 128) ? 4 : 8;
    constexpr int WN = 16 / WM;
    constexpr int MT = 128 / WM;
    constexpr int NT = NOUT / WN;
    constexpr int MB = MT / 16;
    constexpr int N8 = NT / 8;
    constexpr int NBP = NT / 16;
    constexpr int P = 80;
    constexpr int SA = 128 * P;
    constexpr int SB = NOUT * P;
    constexpr int STG = 2 * SA + 2 * SB;
    constexpr int BCH = NOUT * 8;
    // epilogue staging pitch in 32-bit words (16B-aligned, bank-spread)
    constexpr int EP = (NOUT == 128) ? 68 : 36;   // hi/lo word-cols=64 | fp32 cols=32

    extern __shared__ char smem[];
    const uint32_t sb = smem_u32(smem);
    const int tid = threadIdx.x, wid = tid >> 5, L = tid & 31;
    const int warp_m = wid / WN, warp_n = wid % WN;
    const size_t n0 = (size_t)blockIdx.x * 128;

    float acc[MB][N8][4];
#pragma unroll
    for (int i = 0; i < MB; i++)
#pragma unroll
        for (int j = 0; j < N8; j++)
#pragma unroll
            for (int q = 0; q < 4; q++) acc[i][j][q] = 0.f;

    auto load_tile = [&](int t, int stage) {
        uint32_t base = sb + stage * STG;
#pragma unroll
        for (int it = 0; it < 2; it++) {
            int idx = tid + it * 512;
            int buf = idx >> 9, rem = idx & 511;
            int row = rem >> 2, c = rem & 3;
            const __nv_bfloat16* src = (buf ? g_adj_lo : g_adj_hi)
                                       + (n0 + row) * NAP + t * KT + c * 8;
            cpa(base + buf * SA + row * P + c * 16, src);
        }
        if (tid < BCH) {
            int buf = tid / (BCH / 2), rem = tid % (BCH / 2);
            int row = rem >> 2, c = rem & 3;
            const __nv_bfloat16* src = (buf ? g_MT_lo : g_MT_hi) + row * NAP + t * KT + c * 8;
            cpa(base + 2 * SA + buf * SB + row * P + c * 16, src);
        }
        if (BCH > 512 && tid + 512 < BCH) {
            int idx = tid + 512;
            int buf = idx / (BCH / 2), rem = idx % (BCH / 2);
            int row = rem >> 2, c = rem & 3;
            const __nv_bfloat16* src = (buf ? g_MT_lo : g_MT_hi) + row * NAP + t * KT + c * 8;
            cpa(base + 2 * SA + buf * SB + row * P + c * 16, src);
        }
    };

    load_tile(0, 0);
    cpa_commit();

    const int T = NAP / KT;  // 10
    for (int t = 0; t < T; t++) {
        cpa_wait<0>();
        __syncthreads();
        if (t + 1 < T) {
            load_tile(t + 1, (t + 1) & 1);
            cpa_commit();
        }
        const uint32_t st = sb + (t & 1) * STG;
        const uint32_t Ah = st, Al = st + SA;
        const uint32_t Bh = st + 2 * SA, Bl = Bh + SB;

#pragma unroll
        for (int ks = 0; ks < 2; ks++) {
            const uint32_t aoff = (uint32_t)(((L >> 3) & 1) * 8 + (L & 7)) * P
                                + ks * 32 + ((L >> 4) & 1) * 16;
            uint32_t AF[2][MB][4];
#pragma unroll
            for (int mb = 0; mb < MB; mb++) {
                uint32_t ro = (uint32_t)(warp_m * MT + mb * 16) * P;
                ldm4(AF[0][mb], Ah + ro + aoff);
                ldm4(AF[1][mb], Al + ro + aoff);
            }
            const uint32_t boff = (uint32_t)(((L >> 4) & 1) * 8 + (L & 7)) * P
                                + ks * 32 + ((L >> 3) & 1) * 16;
            uint32_t BF[2][NBP][4];
#pragma unroll
            for (int nb = 0; nb < NBP; nb++) {
                uint32_t ro = (uint32_t)(warp_n * NT + nb * 16) * P;
                ldm4(BF[0][nb], Bh + ro + boff);
                ldm4(BF[1][nb], Bl + ro + boff);
            }
#pragma unroll
            for (int mb = 0; mb < MB; mb++)
#pragma unroll
                for (int j = 0; j < N8; j++) {
                    const uint32_t* bh = &BF[0][j >> 1][(j & 1) * 2];
                    const uint32_t* bl = &BF[1][j >> 1][(j & 1) * 2];
                    mma16816(acc[mb][j], AF[0][mb], bh);
                    mma16816(acc[mb][j], AF[0][mb], bl);
                    mma16816(acc[mb][j], AF[1][mb], bh);
                }
        }
    }

    // ---------------- epilogue: smem staging + coalesced stores ----------------
    __syncthreads();   // all warps done with pipeline buffers; reuse as staging

    if (FINAL) {
        // stage fp32 out block [128][NC] with pitch EP=36 words
        float* stg = reinterpret_cast<float*>(smem);
#pragma unroll
        for (int mb = 0; mb < MB; mb++) {
            int r0 = warp_m * MT + mb * 16 + (L >> 2);
            size_t gr0 = n0 + r0;
            float ri0 = (gr0 < NN) ? 1.f / fmaxf(g_rowsum[gr0], 1e-12f) : 0.f;
            float ri1 = (gr0 + 8 < NN) ? 1.f / fmaxf(g_rowsum[gr0 + 8], 1e-12f) : 0.f;
#pragma unroll
            for (int j = 0; j < N8; j++) {
                int d = warp_n * NT + j * 8 + (L & 3) * 2;
                stg[r0 * EP + d]           = acc[mb][j][0] * ri0;
                stg[r0 * EP + d + 1]       = acc[mb][j][1] * ri0;
                stg[(r0 + 8) * EP + d]     = acc[mb][j][2] * ri1;
                stg[(r0 + 8) * EP + d + 1] = acc[mb][j][3] * ri1;
            }
        }
        __syncthreads();
        // coalesced copy: 128 rows x 8 uint4 = 1024 chunks
#pragma unroll
        for (int p = 0; p < 2; p++) {
            int idx = tid + p * 512;
            int r = idx >> 3, c4 = idx & 7;
            if (n0 + r < NN) {
                float4 v = *reinterpret_cast<float4*>(&stg[r * EP + c4 * 4]);
                *reinterpret_cast<float4*>(out + (n0 + r) * NC + c4 * 4) = v;
            }
        }
    } else {
        // stage hi and lo planes [128][64 words] pitch EP=68 words each
        uint32_t* sh = reinterpret_cast<uint32_t*>(smem);
        uint32_t* sl = sh + 128 * EP;
#pragma unroll
        for (int mb = 0; mb < MB; mb++) {
            int r0 = warp_m * MT + mb * 16 + (L >> 2);
            size_t gr0 = n0 + r0;
            float ri0 = (gr0 < NN) ? 1.f / fmaxf(g_rowsum[gr0], 1e-12f) : 0.f;
            float ri1 = (gr0 + 8 < NN) ? 1.f / fmaxf(g_rowsum[gr0 + 8], 1e-12f) : 0.f;
#pragma unroll
            for (int j = 0; j < N8; j++) {
                int dw = (warp_n * NT + j * 8) / 2 + (L & 3);   // word col
                uint32_t hi, lo;
                split2(fmaxf(acc[mb][j][0] * ri0, 0.f),
                       fmaxf(acc[mb][j][1] * ri0, 0.f), hi, lo);
                sh[r0 * EP + dw] = hi;
                sl[r0 * EP + dw] = lo;
                split2(fmaxf(acc[mb][j][2] * ri1, 0.f),
                       fmaxf(acc[mb][j][3] * ri1, 0.f), hi, lo);
                sh[(r0 + 8) * EP + dw] = hi;
                sl[(r0 + 8) * EP + dw] = lo;
            }
        }
        __syncthreads();
        // coalesced copy: per plane 128 rows x 16 uint4 = 2048 chunks
#pragma unroll
        for (int p = 0; p < 4; p++) {
            int idx = tid + p * 512;
            int r = idx >> 4, c4 = idx & 15;
            if (n0 + r < NN) {
                uint4 vh = *reinterpret_cast<uint4*>(&sh[r * EP + c4 * 4]);
                uint4 vl = *reinterpret_cast<uint4*>(&sl[r * EP + c4 * 4]);
                *reinterpret_cast<uint4*>(g_hh + (n0 + r) * NF + c4 * 8) = vh;
                *reinterpret_cast<uint4*>(g_hl + (n0 + r) * NF + c4 * 8) = vl;
            }
        }
    }
}

// ---------------------------------------------------------------------------
extern "C" void kernel_launch(void* const* d_in, const int* in_sizes, int n_in,
                              void* d_out, int out_size) {
    const float* x   = (const float*)d_in[0];
    const float* adj = (const float*)d_in[1];
    const float* W1  = (const float*)d_in[2];
    const float* W2  = (const float*)d_in[3];
    const float* W3  = (const float*)d_in[4];
    float* out = (float*)d_out;

    cudaFuncSetAttribute(upass_kernel,
                         cudaFuncAttributeMaxDynamicSharedMemorySize, 2 * U_STG128);
    cudaFuncSetAttribute(ppass_kernel<128, false>,
                         cudaFuncAttributeMaxDynamicSharedMemorySize, 81920);
    cudaFuncSetAttribute(ppass_kernel<32, true>,
                         cudaFuncAttributeMaxDynamicSharedMemorySize, 51200);

    init_kernel<<<440, 256>>>();
    conv_adj_kernel<<<800, 256>>>(adj);
    conv_x_kernel<<<25600, 256>>>(x);

    dim3 ugrid(3, NSLICE);

    upass_kernel<<<ugrid, 256, 2 * U_STG128>>>();
    mkM_kernel<128><<<150, 256>>>(W1);
    ppass_kernel<128, false><<<1563, 512, 81920>>>(nullptr);

    upass_kernel<<<ugrid, 256, 2 * U_STG128>>>();
    mkM_kernel<128><<<150, 256>>>(W2);
    ppass_kernel<128, false><<<1563, 512, 81920>>>(nullptr);

    upass_kernel<<<ugrid, 256, 2 * U_STG128>>>();
    mkM_kernel<32><<<150, 256>>>(W3);
    ppass_kernel<32, true><<<1563, 512, 51200>>>(out);
}

// round 14
// speedup vs baseline: 1.3106x; 1.2773x over previous
#include <cuda_runtime.h>
#include <cuda_fp16.h>
#include <cstdint>

#define NN 200000
#define PADK 200704
#define NA 300
#define NAP 320
#define NF 128
#define NC 32

#define SLICE_K 2048
#define NSLICE 98
#define KT 32

// ---------------- device scratch (row-padded to PADK) ----------------
__device__ __half g_adj[(size_t)PADK * NAP];      // single fp16 adj
__device__ __half g_hh[(size_t)PADK * NF];        // h hi
__device__ __half g_hl[(size_t)PADK * NF];        // h lo (residual)
__device__ float g_U[384 * NF];
__device__ __half g_MT_hi[NF * NAP];
__device__ __half g_MT_lo[NF * NAP];
__device__ float g_rowsum[NN];
__device__ float g_colsum[384];

// ---------------- helpers ----------------
__device__ __forceinline__ uint32_t smem_u32(const void* p) {
    uint32_t a;
    asm("{ .reg .u64 t; cvta.to.shared.u64 t, %1; cvt.u32.u64 %0, t; }"
        : "=r"(a) : "l"(p));
    return a;
}
__device__ __forceinline__ void cpa(uint32_t dst, const void* src) {
    asm volatile("cp.async.cg.shared.global [%0], [%1], 16;"
                 :: "r"(dst), "l"(src) : "memory");
}
__device__ __forceinline__ void cpa_commit() {
    asm volatile("cp.async.commit_group;" ::: "memory");
}
template<int N> __device__ __forceinline__ void cpa_wait() {
    asm volatile("cp.async.wait_group %0;" :: "n"(N) : "memory");
}
__device__ __forceinline__ void ldm4(uint32_t* r, uint32_t a) {
    asm volatile("ldmatrix.sync.aligned.m8n8.x4.shared.b16 {%0,%1,%2,%3}, [%4];"
        : "=r"(r[0]), "=r"(r[1]), "=r"(r[2]), "=r"(r[3]) : "r"(a));
}
__device__ __forceinline__ void ldm4t(uint32_t* r, uint32_t a) {
    asm volatile("ldmatrix.sync.aligned.m8n8.x4.trans.shared.b16 {%0,%1,%2,%3}, [%4];"
        : "=r"(r[0]), "=r"(r[1]), "=r"(r[2]), "=r"(r[3]) : "r"(a));
}
__device__ __forceinline__ void mma16816(float* d, const uint32_t* a, const uint32_t* b) {
    asm volatile("mma.sync.aligned.m16n8k16.row.col.f32.f16.f16.f32 "
        "{%0,%1,%2,%3}, {%4,%5,%6,%7}, {%8,%9}, {%0,%1,%2,%3};"
        : "+f"(d[0]), "+f"(d[1]), "+f"(d[2]), "+f"(d[3])
        : "r"(a[0]), "r"(a[1]), "r"(a[2]), "r"(a[3]), "r"(b[0]), "r"(b[1]));
}

__device__ __forceinline__ void split1(float v, __half& h, __half& l) {
    h = __float2half(v);
    l = __float2half(v - __half2float(h));
}
__device__ __forceinline__ void split2(float v0, float v1, uint32_t& hi, uint32_t& lo) {
    __half h0, l0, h1, l1;
    split1(v0, h0, l0); split1(v1, h1, l1);
    __half2 hp = __halves2half2(h0, h1);
    __half2 lp = __halves2half2(l0, l1);
    hi = *reinterpret_cast<uint32_t*>(&hp);
    lo = *reinterpret_cast<uint32_t*>(&lp);
}
__device__ __forceinline__ uint32_t pack2h(float v0, float v1) {
    __half2 p = __halves2half2(__float2half(v0), __float2half(v1));
    return *reinterpret_cast<uint32_t*>(&p);
}

// ---------------------------------------------------------------------------
#define PADR (PADK - NN)
__global__ void init_kernel() {
    int i = blockIdx.x * blockDim.x + threadIdx.x;
    if (i < 384 * NF) g_U[i] = 0.f;
    if (i < 384) g_colsum[i] = 0.f;
    if (i < NF * NAP / 2) {
        reinterpret_cast<uint32_t*>(g_MT_hi)[i] = 0u;
        reinterpret_cast<uint32_t*>(g_MT_lo)[i] = 0u;
    }
    if (i < PADR * NAP / 2)
        reinterpret_cast<uint32_t*>(g_adj + (size_t)NN * NAP)[i] = 0u;
    if (i < PADR * NF / 2) {
        reinterpret_cast<uint32_t*>(g_hh + (size_t)NN * NF)[i] = 0u;
        reinterpret_cast<uint32_t*>(g_hl + (size_t)NN * NF)[i] = 0u;
    }
}

// ---------------------------------------------------------------------------
// adj -> single fp16 (padded 320 cols) + rowsum + colsum in one pass
// ---------------------------------------------------------------------------
__device__ __forceinline__ void w4h(__half* ph, float4 v) {
    uint2 o;
    o.x = pack2h(v.x, v.y);
    o.y = pack2h(v.z, v.w);
    *reinterpret_cast<uint2*>(ph) = o;
}

#define CONV_ROWS 250
__global__ void __launch_bounds__(256) conv_adj_kernel(const float* __restrict__ adj) {
    const int tx = threadIdx.x & 31;
    const int ty = threadIdx.x >> 5;
    const int r0 = blockIdx.x * CONV_ROWS;
    const int r1 = min(r0 + CONV_ROWS, NN);

    float ca[12];
#pragma unroll
    for (int j = 0; j < 12; j++) ca[j] = 0.f;

    for (int r = r0 + ty; r < r1; r += 8) {
        const float4* row4 = (const float4*)(adj + (size_t)r * NA);
        float4 v0 = row4[tx];
        float4 v1 = row4[32 + tx];
        float4 v2 = (tx < 11) ? row4[64 + tx] : make_float4(0.f, 0.f, 0.f, 0.f);
        ca[0] += v0.x; ca[1] += v0.y; ca[2]  += v0.z; ca[3]  += v0.w;
        ca[4] += v1.x; ca[5] += v1.y; ca[6]  += v1.z; ca[7]  += v1.w;
        ca[8] += v2.x; ca[9] += v2.y; ca[10] += v2.z; ca[11] += v2.w;
        float rp = v0.x + v0.y + v0.z + v0.w
                 + v1.x + v1.y + v1.z + v1.w
                 + v2.x + v2.y + v2.z + v2.w;
#pragma unroll
        for (int o = 16; o > 0; o >>= 1)
            rp += __shfl_down_sync(0xffffffffu, rp, o);
        if (tx == 0) g_rowsum[r] = rp;

        __half* oh = g_adj + (size_t)r * NAP;
        w4h(oh + 4 * tx, v0);
        w4h(oh + 4 * (32 + tx), v1);
        if (tx < 16) w4h(oh + 4 * (64 + tx), v2);
    }

    __shared__ float sc[8][12][32];
#pragma unroll
    for (int j = 0; j < 12; j++) sc[ty][j][tx] = ca[j];
    __syncthreads();
    if (ty == 0) {
#pragma unroll
        for (int j = 0; j < 12; j++) {
            float s = 0.f;
#pragma unroll
            for (int t = 0; t < 8; t++) s += sc[t][j][tx];
            int col = (j >> 2) * 128 + tx * 4 + (j & 3);
            if (col < NA) atomicAdd(&g_colsum[col], s);
        }
    }
}

// ---------------------------------------------------------------------------
__global__ void conv_x_kernel(const float* __restrict__ x) {
    size_t i = (size_t)blockIdx.x * blockDim.x + threadIdx.x;
    if (i < (size_t)NN * NF / 4) {
        float4 v = ((const float4*)x)[i];
        uint32_t hA, lA, hB, lB;
        split2(v.x, v.y, hA, lA);
        split2(v.z, v.w, hB, lB);
        *reinterpret_cast<uint2*>(g_hh + 4 * i) = make_uint2(hA, hB);
        *reinterpret_cast<uint2*>(g_hl + 4 * i) = make_uint2(lA, lB);
    }
}

// ---------------------------------------------------------------------------
// upass: U[a][d] += sum_k adj[k][a]*h[k][d].  grid(3, 98): chunks {128,128,64}.
// 256 thr, 2-stage pipeline. A = adj single fp16; B = h hi/lo (2 MMA terms).
// ---------------------------------------------------------------------------
template<int AW>
__device__ __forceinline__ void upass_body(uint32_t sb, int a0, size_t k0, int tid) {
    constexpr int PA  = AW * 2 + 16;      // 272 or 144
    constexpr int PB  = 272;
    constexpr int SAB = KT * PA;          // single A buf
    constexpr int SBB = KT * PB;
    constexpr int STG = SAB + 2 * SBB;
    constexpr int WN  = (AW == 128) ? 2 : 4;
    constexpr int ND  = 128 / WN;
    constexpr int N8  = ND / 8;
    constexpr int NBP = ND / 16;
    constexpr int ACH = KT * (AW / 8);    // 512 or 256 chunks (1 buf)

    const int wid = tid >> 5, L = tid & 31;
    const int warp_m = wid / WN, warp_n = wid % WN;

    float acc[2][N8][4];
#pragma unroll
    for (int i = 0; i < 2; i++)
#pragma unroll
        for (int j = 0; j < N8; j++)
#pragma unroll
            for (int q = 0; q < 4; q++) acc[i][j][q] = 0.f;

    auto load = [&](uint32_t base, size_t kt) {
#pragma unroll
        for (int it = 0; it < ACH / 256; it++) {
            int idx = tid + it * 256;
            int row = idx / (AW / 8), c = idx % (AW / 8);
            const __half* src = g_adj + (kt + row) * NAP + a0 + c * 8;
            cpa(base + row * PA + c * 16, src);
        }
#pragma unroll
        for (int it = 0; it < 4; it++) {     // B: 2 bufs x 512 chunks
            int idx = tid + it * 256;
            int buf = idx >> 9, rem = idx & 511;
            int row = rem >> 4, c = rem & 15;
            const __half* src = (buf ? g_hl : g_hh) + (kt + row) * NF + c * 8;
            cpa(base + SAB + buf * SBB + row * PB + c * 16, src);
        }
    };

    load(sb, k0);
    cpa_commit();

    const int T = SLICE_K / KT;  // 64
    for (int t = 0; t < T; t++) {
        cpa_wait<0>();
        __syncthreads();
        if (t + 1 < T) {
            load(sb + ((t + 1) & 1) * STG, k0 + (size_t)(t + 1) * KT);
            cpa_commit();
        }
        const uint32_t st = sb + (t & 1) * STG;
        const uint32_t Ah = st;
        const uint32_t Bh = st + SAB, Bl = Bh + SBB;

#pragma unroll
        for (int ks = 0; ks < 2; ks++) {
            const uint32_t aoff = (uint32_t)(ks * 16 + ((L >> 4) & 1) * 8 + (L & 7)) * PA
                                + ((L >> 3) & 1) * 16;
            uint32_t AF[2][4];
#pragma unroll
            for (int mb = 0; mb < 2; mb++) {
                uint32_t c2 = (uint32_t)(warp_m * 32 + mb * 16) * 2;
                ldm4t(AF[mb], Ah + aoff + c2);
            }
            const uint32_t boff = (uint32_t)(ks * 16 + ((L >> 3) & 1) * 8 + (L & 7)) * PB
                                + ((L >> 4) & 1) * 16;
#pragma unroll
            for (int nb = 0; nb < NBP; nb++) {
                uint32_t BH[4], BL[4];
                uint32_t c2 = (uint32_t)(warp_n * ND + nb * 16) * 2;
                ldm4t(BH, Bh + boff + c2);
                ldm4t(BL, Bl + boff + c2);
#pragma unroll
                for (int mb = 0; mb < 2; mb++)
#pragma unroll
                    for (int jj = 0; jj < 2; jj++) {
                        mma16816(acc[mb][nb * 2 + jj], AF[mb], &BH[jj * 2]);
                        mma16816(acc[mb][nb * 2 + jj], AF[mb], &BL[jj * 2]);
                    }
            }
        }
    }

#pragma unroll
    for (int mb = 0; mb < 2; mb++) {
        int a = a0 + warp_m * 32 + mb * 16 + (L >> 2);
#pragma unroll
        for (int j = 0; j < N8; j++) {
            int d = warp_n * ND + j * 8 + (L & 3) * 2;
            if (a < NA) {
                atomicAdd(&g_U[a * NF + d],     acc[mb][j][0]);
                atomicAdd(&g_U[a * NF + d + 1], acc[mb][j][1]);
            }
            if (a + 8 < NA) {
                atomicAdd(&g_U[(a + 8) * NF + d],     acc[mb][j][2]);
                atomicAdd(&g_U[(a + 8) * NF + d + 1], acc[mb][j][3]);
            }
        }
    }
}

#define U_STG128 (KT * 272 + 2 * (KT * 272))   // 26112
__global__ void __launch_bounds__(256, 2) upass_kernel() {
    extern __shared__ char smem[];
    const uint32_t sb = smem_u32(smem);
    const size_t k0 = (size_t)blockIdx.y * SLICE_K;
    if (blockIdx.x < 2)
        upass_body<128>(sb, blockIdx.x * 128, k0, threadIdx.x);
    else
        upass_body<64>(sb, 256, k0, threadIdx.x);
}

// ---------------------------------------------------------------------------
// mkM: two anchors per CTA. M^T = (U@W)/clamp(colsum) fp16 hi/lo; zero U row.
// ---------------------------------------------------------------------------
template<int DOUT>
__global__ void mkM_kernel(const float* __restrict__ W) {
    __shared__ float u_s[2][NF];
    const int half = threadIdx.x >> 7;
    const int d = threadIdx.x & 127;
    const int a = blockIdx.x * 2 + half;
    u_s[half][d] = g_U[a * NF + d];
    __syncthreads();
    g_U[a * NF + d] = 0.f;
    if (d < DOUT) {
        float cinv = 1.f / fmaxf(g_colsum[a], 1e-12f);
        float acc = 0.f;
#pragma unroll 8
        for (int k = 0; k < NF; k++)
            acc += u_s[half][k] * W[k * DOUT + d];
        __half hb, lb;
        split1(acc * cinv, hb, lb);
        g_MT_hi[d * NAP + a] = hb;
        g_MT_lo[d * NAP + a] = lb;
    }
}

// ---------------------------------------------------------------------------
// ppass: C[n][d] = sum_a adj[n][a]*M[a][d]; 512 thr, 2-stage pipeline.
// A = adj single fp16; B = MT hi/lo (2 MMA terms). Coalesced smem epilogue.
// ---------------------------------------------------------------------------
template<int NOUT, bool FINAL>
__global__ void __launch_bounds__(512) ppass_kernel(float* __restrict__ out) {
    constexpr int WM = (NOUT == 128) ? 4 : 8;
    constexpr int WN = 16 / WM;
    constexpr int MT = 128 / WM;
    constexpr int NT = NOUT / WN;
    constexpr int MB = MT / 16;
    constexpr int N8 = NT / 8;
    constexpr int NBP = NT / 16;
    constexpr int P = 80;
    constexpr int SA = 128 * P;          // single A buf
    constexpr int SB = NOUT * P;
    constexpr int STG = SA + 2 * SB;
    constexpr int BCH = NOUT * 8;        // B chunks (2 bufs)
    constexpr int EP = (NOUT == 128) ? 68 : 36;

    extern __shared__ char smem[];
    const uint32_t sb = smem_u32(smem);
    const int tid = threadIdx.x, wid = tid >> 5, L = tid & 31;
    const int warp_m = wid / WN, warp_n = wid % WN;
    const size_t n0 = (size_t)blockIdx.x * 128;

    float acc[MB][N8][4];
#pragma unroll
    for (int i = 0; i < MB; i++)
#pragma unroll
        for (int j = 0; j < N8; j++)
#pragma unroll
            for (int q = 0; q < 4; q++) acc[i][j][q] = 0.f;

    auto load_tile = [&](int t, int stage) {
        uint32_t base = sb + stage * STG;
        {   // A: 512 chunks (single buf)
            int row = tid >> 2, c = tid & 3;
            const __half* src = g_adj + (n0 + row) * NAP + t * KT + c * 8;
            cpa(base + row * P + c * 16, src);
        }
        if (tid < BCH) {
            int buf = tid / (BCH / 2), rem = tid % (BCH / 2);
            int row = rem >> 2, c = rem & 3;
            const __half* src = (buf ? g_MT_lo : g_MT_hi) + row * NAP + t * KT + c * 8;
            cpa(base + SA + buf * SB + row * P + c * 16, src);
        }
        if (BCH > 512 && tid + 512 < BCH) {
            int idx = tid + 512;
            int buf = idx / (BCH / 2), rem = idx % (BCH / 2);
            int row = rem >> 2, c = rem & 3;
            const __half* src = (buf ? g_MT_lo : g_MT_hi) + row * NAP + t * KT + c * 8;
            cpa(base + SA + buf * SB + row * P + c * 16, src);
        }
    };

    load_tile(0, 0);
    cpa_commit();

    const int T = NAP / KT;  // 10
    for (int t = 0; t < T; t++) {
        cpa_wait<0>();
        __syncthreads();
        if (t + 1 < T) {
            load_tile(t + 1, (t + 1) & 1);
            cpa_commit();
        }
        const uint32_t st = sb + (t & 1) * STG;
        const uint32_t Ah = st;
        const uint32_t Bh = st + SA, Bl = Bh + SB;

#pragma unroll
        for (int ks = 0; ks < 2; ks++) {
            const uint32_t aoff = (uint32_t)(((L >> 3) & 1) * 8 + (L & 7)) * P
                                + ks * 32 + ((L >> 4) & 1) * 16;
            uint32_t AF[MB][4];
#pragma unroll
            for (int mb = 0; mb < MB; mb++) {
                uint32_t ro = (uint32_t)(warp_m * MT + mb * 16) * P;
                ldm4(AF[mb], Ah + ro + aoff);
            }
            const uint32_t boff = (uint32_t)(((L >> 4) & 1) * 8 + (L & 7)) * P
                                + ks * 32 + ((L >> 3) & 1) * 16;
            uint32_t BF[2][NBP][4];
#pragma unroll
            for (int nb = 0; nb < NBP; nb++) {
                uint32_t ro = (uint32_t)(warp_n * NT + nb * 16) * P;
                ldm4(BF[0][nb], Bh + ro + boff);
                ldm4(BF[1][nb], Bl + ro + boff);
            }
#pragma unroll
            for (int mb = 0; mb < MB; mb++)
#pragma unroll
                for (int j = 0; j < N8; j++) {
                    const uint32_t* bh = &BF[0][j >> 1][(j & 1) * 2];
                    const uint32_t* bl = &BF[1][j >> 1][(j & 1) * 2];
                    mma16816(acc[mb][j], AF[mb], bh);
                    mma16816(acc[mb][j], AF[mb], bl);
                }
        }
    }

    // ---------------- epilogue: smem staging + coalesced stores ----------------
    __syncthreads();

    if (FINAL) {
        float* stg = reinterpret_cast<float*>(smem);
#pragma unroll
        for (int mb = 0; mb < MB; mb++) {
            int r0 = warp_m * MT + mb * 16 + (L >> 2);
            size_t gr0 = n0 + r0;
            float ri0 = (gr0 < NN) ? 1.f / fmaxf(g_rowsum[gr0], 1e-12f) : 0.f;
            float ri1 = (gr0 + 8 < NN) ? 1.f / fmaxf(g_rowsum[gr0 + 8], 1e-12f) : 0.f;
#pragma unroll
            for (int j = 0; j < N8; j++) {
                int d = warp_n * NT + j * 8 + (L & 3) * 2;
                stg[r0 * EP + d]           = acc[mb][j][0] * ri0;
                stg[r0 * EP + d + 1]       = acc[mb][j][1] * ri0;
                stg[(r0 + 8) * EP + d]     = acc[mb][j][2] * ri1;
                stg[(r0 + 8) * EP + d + 1] = acc[mb][j][3] * ri1;
            }
        }
        __syncthreads();
#pragma unroll
        for (int p = 0; p < 2; p++) {
            int idx = tid + p * 512;
            int r = idx >> 3, c4 = idx & 7;
            if (n0 + r < NN) {
                float4 v = *reinterpret_cast<float4*>(&stg[r * EP + c4 * 4]);
                *reinterpret_cast<float4*>(out + (n0 + r) * NC + c4 * 4) = v;
            }
        }
    } else {
        uint32_t* sh = reinterpret_cast<uint32_t*>(smem);
        uint32_t* sl = sh + 128 * EP;
#pragma unroll
        for (int mb = 0; mb < MB; mb++) {
            int r0 = warp_m * MT + mb * 16 + (L >> 2);
            size_t gr0 = n0 + r0;
            float ri0 = (gr0 < NN) ? 1.f / fmaxf(g_rowsum[gr0], 1e-12f) : 0.f;
            float ri1 = (gr0 + 8 < NN) ? 1.f / fmaxf(g_rowsum[gr0 + 8], 1e-12f) : 0.f;
#pragma unroll
            for (int j = 0; j < N8; j++) {
                int dw = (warp_n * NT + j * 8) / 2 + (L & 3);
                uint32_t hi, lo;
                split2(fmaxf(acc[mb][j][0] * ri0, 0.f),
                       fmaxf(acc[mb][j][1] * ri0, 0.f), hi, lo);
                sh[r0 * EP + dw] = hi;
                sl[r0 * EP + dw] = lo;
                split2(fmaxf(acc[mb][j][2] * ri1, 0.f),
                       fmaxf(acc[mb][j][3] * ri1, 0.f), hi, lo);
                sh[(r0 + 8) * EP + dw] = hi;
                sl[(r0 + 8) * EP + dw] = lo;
            }
        }
        __syncthreads();
#pragma unroll
        for (int p = 0; p < 4; p++) {
            int idx = tid + p * 512;
            int r = idx >> 4, c4 = idx & 15;
            if (n0 + r < NN) {
                uint4 vh = *reinterpret_cast<uint4*>(&sh[r * EP + c4 * 4]);
                uint4 vl = *reinterpret_cast<uint4*>(&sl[r * EP + c4 * 4]);
                *reinterpret_cast<uint4*>(g_hh + (n0 + r) * NF + c4 * 8) = vh;
                *reinterpret_cast<uint4*>(g_hl + (n0 + r) * NF + c4 * 8) = vl;
            }
        }
    }
}

// ---------------------------------------------------------------------------
extern "C" void kernel_launch(void* const* d_in, const int* in_sizes, int n_in,
                              void* d_out, int out_size) {
    const float* x   = (const float*)d_in[0];
    const float* adj = (const float*)d_in[1];
    const float* W1  = (const float*)d_in[2];
    const float* W2  = (const float*)d_in[3];
    const float* W3  = (const float*)d_in[4];
    float* out = (float*)d_out;

    // smem: upass 2*26112=52224; ppass<128> max(2*30720, 69632)=69632;
    // ppass<32> max(2*15360, 18432)=30720
    cudaFuncSetAttribute(upass_kernel,
                         cudaFuncAttributeMaxDynamicSharedMemorySize, 2 * U_STG128);
    cudaFuncSetAttribute(ppass_kernel<128, false>,
                         cudaFuncAttributeMaxDynamicSharedMemorySize, 69632);
    cudaFuncSetAttribute(ppass_kernel<32, true>,
                         cudaFuncAttributeMaxDynamicSharedMemorySize, 30720);

    init_kernel<<<440, 256>>>();
    conv_adj_kernel<<<800, 256>>>(adj);
    conv_x_kernel<<<25600, 256>>>(x);

    dim3 ugrid(3, NSLICE);

    upass_kernel<<<ugrid, 256, 2 * U_STG128>>>();
    mkM_kernel<128><<<150, 256>>>(W1);
    ppass_kernel<128, false><<<1563, 512, 69632>>>(nullptr);

    upass_kernel<<<ugrid, 256, 2 * U_STG128>>>();
    mkM_kernel<128><<<150, 256>>>(W2);
    ppass_kernel<128, false><<<1563, 512, 69632>>>(nullptr);

    upass_kernel<<<ugrid, 256, 2 * U_STG128>>>();
    mkM_kernel<32><<<150, 256>>>(W3);
    ppass_kernel<32, true><<<1563, 512, 30720>>>(out);
}

// round 16
// speedup vs baseline: 1.9483x; 1.4865x over previous
#include <cuda_runtime.h>
#include <cuda_fp16.h>
#include <cstdint>

#define NN 200000
#define PADK 200704
#define NA 300
#define NAP 320
#define NF 128
#define NC 32

#define SLICE_K 2048
#define NSLICE 98
#define KT 32

// ---------------- device scratch (row-padded to PADK) ----------------
__device__ __half g_adj[(size_t)PADK * NAP];      // fp16 adj
__device__ __half g_h[(size_t)PADK * NF];         // fp16 hidden
__device__ float g_U[384 * NF];
__device__ __half g_MT[NF * NAP];                 // fp16 M^T
__device__ float g_rowsum[NN];
__device__ float g_colsum[384];

// ---------------- helpers ----------------
__device__ __forceinline__ uint32_t smem_u32(const void* p) {
    uint32_t a;
    asm("{ .reg .u64 t; cvta.to.shared.u64 t, %1; cvt.u32.u64 %0, t; }"
        : "=r"(a) : "l"(p));
    return a;
}
__device__ __forceinline__ void cpa(uint32_t dst, const void* src) {
    asm volatile("cp.async.cg.shared.global [%0], [%1], 16;"
                 :: "r"(dst), "l"(src) : "memory");
}
__device__ __forceinline__ void cpa_commit() {
    asm volatile("cp.async.commit_group;" ::: "memory");
}
template<int N> __device__ __forceinline__ void cpa_wait() {
    asm volatile("cp.async.wait_group %0;" :: "n"(N) : "memory");
}
__device__ __forceinline__ void ldm4(uint32_t* r, uint32_t a) {
    asm volatile("ldmatrix.sync.aligned.m8n8.x4.shared.b16 {%0,%1,%2,%3}, [%4];"
        : "=r"(r[0]), "=r"(r[1]), "=r"(r[2]), "=r"(r[3]) : "r"(a));
}
__device__ __forceinline__ void ldm4t(uint32_t* r, uint32_t a) {
    asm volatile("ldmatrix.sync.aligned.m8n8.x4.trans.shared.b16 {%0,%1,%2,%3}, [%4];"
        : "=r"(r[0]), "=r"(r[1]), "=r"(r[2]), "=r"(r[3]) : "r"(a));
}
__device__ __forceinline__ void mma16816(float* d, const uint32_t* a, const uint32_t* b) {
    asm volatile("mma.sync.aligned.m16n8k16.row.col.f32.f16.f16.f32 "
        "{%0,%1,%2,%3}, {%4,%5,%6,%7}, {%8,%9}, {%0,%1,%2,%3};"
        : "+f"(d[0]), "+f"(d[1]), "+f"(d[2]), "+f"(d[3])
        : "r"(a[0]), "r"(a[1]), "r"(a[2]), "r"(a[3]), "r"(b[0]), "r"(b[1]));
}

__device__ __forceinline__ uint32_t pack2h(float v0, float v1) {
    __half2 p = __halves2half2(__float2half(v0), __float2half(v1));
    return *reinterpret_cast<uint32_t*>(&p);
}

// ---------------------------------------------------------------------------
#define PADR (PADK - NN)
__global__ void init_kernel() {
    int i = blockIdx.x * blockDim.x + threadIdx.x;
    if (i < 384 * NF) g_U[i] = 0.f;
    if (i < 384) g_colsum[i] = 0.f;
    if (i < NF * NAP / 2)
        reinterpret_cast<uint32_t*>(g_MT)[i] = 0u;
    if (i < PADR * NAP / 2)
        reinterpret_cast<uint32_t*>(g_adj + (size_t)NN * NAP)[i] = 0u;
    if (i < PADR * NF / 2)
        reinterpret_cast<uint32_t*>(g_h + (size_t)NN * NF)[i] = 0u;
}

// ---------------------------------------------------------------------------
// adj -> fp16 (padded 320 cols) + rowsum + colsum in one pass
// ---------------------------------------------------------------------------
__device__ __forceinline__ void w4h(__half* ph, float4 v) {
    uint2 o;
    o.x = pack2h(v.x, v.y);
    o.y = pack2h(v.z, v.w);
    *reinterpret_cast<uint2*>(ph) = o;
}

#define CONV_ROWS 250
__global__ void __launch_bounds__(256) conv_adj_kernel(const float* __restrict__ adj) {
    const int tx = threadIdx.x & 31;
    const int ty = threadIdx.x >> 5;
    const int r0 = blockIdx.x * CONV_ROWS;
    const int r1 = min(r0 + CONV_ROWS, NN);

    float ca[12];
#pragma unroll
    for (int j = 0; j < 12; j++) ca[j] = 0.f;

    for (int r = r0 + ty; r < r1; r += 8) {
        const float4* row4 = (const float4*)(adj + (size_t)r * NA);
        float4 v0 = row4[tx];
        float4 v1 = row4[32 + tx];
        float4 v2 = (tx < 11) ? row4[64 + tx] : make_float4(0.f, 0.f, 0.f, 0.f);
        ca[0] += v0.x; ca[1] += v0.y; ca[2]  += v0.z; ca[3]  += v0.w;
        ca[4] += v1.x; ca[5] += v1.y; ca[6]  += v1.z; ca[7]  += v1.w;
        ca[8] += v2.x; ca[9] += v2.y; ca[10] += v2.z; ca[11] += v2.w;
        float rp = v0.x + v0.y + v0.z + v0.w
                 + v1.x + v1.y + v1.z + v1.w
                 + v2.x + v2.y + v2.z + v2.w;
#pragma unroll
        for (int o = 16; o > 0; o >>= 1)
            rp += __shfl_down_sync(0xffffffffu, rp, o);
        if (tx == 0) g_rowsum[r] = rp;

        __half* oh = g_adj + (size_t)r * NAP;
        w4h(oh + 4 * tx, v0);
        w4h(oh + 4 * (32 + tx), v1);
        if (tx < 16) w4h(oh + 4 * (64 + tx), v2);
    }

    __shared__ float sc[8][12][32];
#pragma unroll
    for (int j = 0; j < 12; j++) sc[ty][j][tx] = ca[j];
    __syncthreads();
    if (ty == 0) {
#pragma unroll
        for (int j = 0; j < 12; j++) {
            float s = 0.f;
#pragma unroll
            for (int t = 0; t < 8; t++) s += sc[t][j][tx];
            int col = (j >> 2) * 128 + tx * 4 + (j & 3);
            if (col < NA) atomicAdd(&g_colsum[col], s);
        }
    }
}

// ---------------------------------------------------------------------------
__global__ void conv_x_kernel(const float* __restrict__ x) {
    size_t i = (size_t)blockIdx.x * blockDim.x + threadIdx.x;
    if (i < (size_t)NN * NF / 4) {
        float4 v = ((const float4*)x)[i];
        uint2 o;
        o.x = pack2h(v.x, v.y);
        o.y = pack2h(v.z, v.w);
        *reinterpret_cast<uint2*>(g_h + 4 * i) = o;
    }
}

// ---------------------------------------------------------------------------
// upass: U[a][d] += sum_k adj[k][a]*h[k][d].  grid(3, 98): chunks {128,128,64}.
// 256 thr, 2-stage pipeline. Single fp16 operands, ONE MMA term.
// ---------------------------------------------------------------------------
template<int AW>
__device__ __forceinline__ void upass_body(uint32_t sb, int a0, size_t k0, int tid) {
    constexpr int PA  = AW * 2 + 16;      // 272 or 144
    constexpr int PB  = 272;
    constexpr int SAB = KT * PA;
    constexpr int SBB = KT * PB;
    constexpr int STG = SAB + SBB;
    constexpr int WN  = (AW == 128) ? 2 : 4;
    constexpr int ND  = 128 / WN;
    constexpr int N8  = ND / 8;
    constexpr int NBP = ND / 16;
    constexpr int ACH = KT * (AW / 8);    // 512 or 256

    const int wid = tid >> 5, L = tid & 31;
    const int warp_m = wid / WN, warp_n = wid % WN;

    float acc[2][N8][4];
#pragma unroll
    for (int i = 0; i < 2; i++)
#pragma unroll
        for (int j = 0; j < N8; j++)
#pragma unroll
            for (int q = 0; q < 4; q++) acc[i][j][q] = 0.f;

    auto load = [&](uint32_t base, size_t kt) {
#pragma unroll
        for (int it = 0; it < ACH / 256; it++) {
            int idx = tid + it * 256;
            int row = idx / (AW / 8), c = idx % (AW / 8);
            const __half* src = g_adj + (kt + row) * NAP + a0 + c * 8;
            cpa(base + row * PA + c * 16, src);
        }
#pragma unroll
        for (int it = 0; it < 2; it++) {     // B: 512 chunks (single buf)
            int idx = tid + it * 256;
            int row = idx >> 4, c = idx & 15;
            const __half* src = g_h + (kt + row) * NF + c * 8;
            cpa(base + SAB + row * PB + c * 16, src);
        }
    };

    load(sb, k0);
    cpa_commit();

    const int T = SLICE_K / KT;  // 64
    for (int t = 0; t < T; t++) {
        cpa_wait<0>();
        __syncthreads();
        if (t + 1 < T) {
            load(sb + ((t + 1) & 1) * STG, k0 + (size_t)(t + 1) * KT);
            cpa_commit();
        }
        const uint32_t st = sb + (t & 1) * STG;
        const uint32_t Ah = st;
        const uint32_t Bh = st + SAB;

#pragma unroll
        for (int ks = 0; ks < 2; ks++) {
            const uint32_t aoff = (uint32_t)(ks * 16 + ((L >> 4) & 1) * 8 + (L & 7)) * PA
                                + ((L >> 3) & 1) * 16;
            uint32_t AF[2][4];
#pragma unroll
            for (int mb = 0; mb < 2; mb++) {
                uint32_t c2 = (uint32_t)(warp_m * 32 + mb * 16) * 2;
                ldm4t(AF[mb], Ah + aoff + c2);
            }
            const uint32_t boff = (uint32_t)(ks * 16 + ((L >> 3) & 1) * 8 + (L & 7)) * PB
                                + ((L >> 4) & 1) * 16;
#pragma unroll
            for (int nb = 0; nb < NBP; nb++) {
                uint32_t BH[4];
                uint32_t c2 = (uint32_t)(warp_n * ND + nb * 16) * 2;
                ldm4t(BH, Bh + boff + c2);
#pragma unroll
                for (int mb = 0; mb < 2; mb++)
#pragma unroll
                    for (int jj = 0; jj < 2; jj++)
                        mma16816(acc[mb][nb * 2 + jj], AF[mb], &BH[jj * 2]);
            }
        }
    }

#pragma unroll
    for (int mb = 0; mb < 2; mb++) {
        int a = a0 + warp_m * 32 + mb * 16 + (L >> 2);
#pragma unroll
        for (int j = 0; j < N8; j++) {
            int d = warp_n * ND + j * 8 + (L & 3) * 2;
            if (a < NA) {
                atomicAdd(&g_U[a * NF + d],     acc[mb][j][0]);
                atomicAdd(&g_U[a * NF + d + 1], acc[mb][j][1]);
            }
            if (a + 8 < NA) {
                atomicAdd(&g_U[(a + 8) * NF + d],     acc[mb][j][2]);
                atomicAdd(&g_U[(a + 8) * NF + d + 1], acc[mb][j][3]);
            }
        }
    }
}

#define U_STG128 (KT * 272 + KT * 272)   // 17408
__global__ void __launch_bounds__(256, 2) upass_kernel() {
    extern __shared__ char smem[];
    const uint32_t sb = smem_u32(smem);
    const size_t k0 = (size_t)blockIdx.y * SLICE_K;
    if (blockIdx.x < 2)
        upass_body<128>(sb, blockIdx.x * 128, k0, threadIdx.x);
    else
        upass_body<64>(sb, 256, k0, threadIdx.x);
}

// ---------------------------------------------------------------------------
// mkM: two anchors per CTA. M^T = (U@W)/clamp(colsum) fp16; zero U row.
// ---------------------------------------------------------------------------
template<int DOUT>
__global__ void mkM_kernel(const float* __restrict__ W) {
    __shared__ float u_s[2][NF];
    const int half = threadIdx.x >> 7;
    const int d = threadIdx.x & 127;
    const int a = blockIdx.x * 2 + half;
    u_s[half][d] = g_U[a * NF + d];
    __syncthreads();
    g_U[a * NF + d] = 0.f;
    if (d < DOUT) {
        float cinv = 1.f / fmaxf(g_colsum[a], 1e-12f);
        float acc = 0.f;
#pragma unroll 8
        for (int k = 0; k < NF; k++)
            acc += u_s[half][k] * W[k * DOUT + d];
        g_MT[d * NAP + a] = __float2half(acc * cinv);
    }
}

// ---------------------------------------------------------------------------
// ppass: C[n][d] = sum_a adj[n][a]*M[a][d]; 512 thr, 2-stage pipeline.
// Single fp16 operands, ONE MMA term. Coalesced smem epilogue.
// ---------------------------------------------------------------------------
template<int NOUT, bool FINAL>
__global__ void __launch_bounds__(512) ppass_kernel(float* __restrict__ out) {
    constexpr int WM = (NOUT == 128) ? 4 : 8;
    constexpr int WN = 16 / WM;
    constexpr int MT = 128 / WM;
    constexpr int NT = NOUT / WN;
    constexpr int MB = MT / 16;
    constexpr int N8 = NT / 8;
    constexpr int NBP = NT / 16;
    constexpr int P = 80;
    constexpr int SA = 128 * P;
    constexpr int SB = NOUT * P;
    constexpr int STG = SA + SB;
    constexpr int BCH = NOUT * 4;        // B chunks (single buf)
    constexpr int EP = (NOUT == 128) ? 68 : 36;

    extern __shared__ char smem[];
    const uint32_t sb = smem_u32(smem);
    const int tid = threadIdx.x, wid = tid >> 5, L = tid & 31;
    const int warp_m = wid / WN, warp_n = wid % WN;
    const size_t n0 = (size_t)blockIdx.x * 128;

    float acc[MB][N8][4];
#pragma unroll
    for (int i = 0; i < MB; i++)
#pragma unroll
        for (int j = 0; j < N8; j++)
#pragma unroll
            for (int q = 0; q < 4; q++) acc[i][j][q] = 0.f;

    auto load_tile = [&](int t, int stage) {
        uint32_t base = sb + stage * STG;
        {   // A: 512 chunks
            int row = tid >> 2, c = tid & 3;
            const __half* src = g_adj + (n0 + row) * NAP + t * KT + c * 8;
            cpa(base + row * P + c * 16, src);
        }
        if (tid < BCH) {
            int row = tid >> 2, c = tid & 3;
            const __half* src = g_MT + row * NAP + t * KT + c * 8;
            cpa(base + SA + row * P + c * 16, src);
        }
    };

    load_tile(0, 0);
    cpa_commit();

    const int T = NAP / KT;  // 10
    for (int t = 0; t < T; t++) {
        cpa_wait<0>();
        __syncthreads();
        if (t + 1 < T) {
            load_tile(t + 1, (t + 1) & 1);
            cpa_commit();
        }
        const uint32_t st = sb + (t & 1) * STG;
        const uint32_t Ah = st;
        const uint32_t Bh = st + SA;

#pragma unroll
        for (int ks = 0; ks < 2; ks++) {
            const uint32_t aoff = (uint32_t)(((L >> 3) & 1) * 8 + (L & 7)) * P
                                + ks * 32 + ((L >> 4) & 1) * 16;
            uint32_t AF[MB][4];
#pragma unroll
            for (int mb = 0; mb < MB; mb++) {
                uint32_t ro = (uint32_t)(warp_m * MT + mb * 16) * P;
                ldm4(AF[mb], Ah + ro + aoff);
            }
            const uint32_t boff = (uint32_t)(((L >> 4) & 1) * 8 + (L & 7)) * P
                                + ks * 32 + ((L >> 3) & 1) * 16;
            uint32_t BF[NBP][4];
#pragma unroll
            for (int nb = 0; nb < NBP; nb++) {
                uint32_t ro = (uint32_t)(warp_n * NT + nb * 16) * P;
                ldm4(BF[nb], Bh + ro + boff);
            }
#pragma unroll
            for (int mb = 0; mb < MB; mb++)
#pragma unroll
                for (int j = 0; j < N8; j++)
                    mma16816(acc[mb][j], AF[mb], &BF[j >> 1][(j & 1) * 2]);
        }
    }

    // ---------------- epilogue: smem staging + coalesced stores ----------------
    __syncthreads();

    if (FINAL) {
        float* stg = reinterpret_cast<float*>(smem);
#pragma unroll
        for (int mb = 0; mb < MB; mb++) {
            int r0 = warp_m * MT + mb * 16 + (L >> 2);
            size_t gr0 = n0 + r0;
            float ri0 = (gr0 < NN) ? 1.f / fmaxf(g_rowsum[gr0], 1e-12f) : 0.f;
            float ri1 = (gr0 + 8 < NN) ? 1.f / fmaxf(g_rowsum[gr0 + 8], 1e-12f) : 0.f;
#pragma unroll
            for (int j = 0; j < N8; j++) {
                int d = warp_n * NT + j * 8 + (L & 3) * 2;
                stg[r0 * EP + d]           = acc[mb][j][0] * ri0;
                stg[r0 * EP + d + 1]       = acc[mb][j][1] * ri0;
                stg[(r0 + 8) * EP + d]     = acc[mb][j][2] * ri1;
                stg[(r0 + 8) * EP + d + 1] = acc[mb][j][3] * ri1;
            }
        }
        __syncthreads();
#pragma unroll
        for (int p = 0; p < 2; p++) {
            int idx = tid + p * 512;
            int r = idx >> 3, c4 = idx & 7;
            if (n0 + r < NN) {
                float4 v = *reinterpret_cast<float4*>(&stg[r * EP + c4 * 4]);
                *reinterpret_cast<float4*>(out + (n0 + r) * NC + c4 * 4) = v;
            }
        }
    } else {
        uint32_t* sh = reinterpret_cast<uint32_t*>(smem);
#pragma unroll
        for (int mb = 0; mb < MB; mb++) {
            int r0 = warp_m * MT + mb * 16 + (L >> 2);
            size_t gr0 = n0 + r0;
            float ri0 = (gr0 < NN) ? 1.f / fmaxf(g_rowsum[gr0], 1e-12f) : 0.f;
            float ri1 = (gr0 + 8 < NN) ? 1.f / fmaxf(g_rowsum[gr0 + 8], 1e-12f) : 0.f;
#pragma unroll
            for (int j = 0; j < N8; j++) {
                int dw = (warp_n * NT + j * 8) / 2 + (L & 3);
                sh[r0 * EP + dw] = pack2h(fmaxf(acc[mb][j][0] * ri0, 0.f),
                                          fmaxf(acc[mb][j][1] * ri0, 0.f));
                sh[(r0 + 8) * EP + dw] = pack2h(fmaxf(acc[mb][j][2] * ri1, 0.f),
                                                fmaxf(acc[mb][j][3] * ri1, 0.f));
            }
        }
        __syncthreads();
        // FIX (R15 bug): need 2048 chunks (128 rows x 16 uint4), was 1024 ->
        // only half the h rows were written and layers 2-3 read garbage.
#pragma unroll
        for (int p = 0; p < 4; p++) {
            int idx = tid + p * 512;
            int r = idx >> 4, c4 = idx & 15;
            if (n0 + r < NN) {
                uint4 vh = *reinterpret_cast<uint4*>(&sh[r * EP + c4 * 4]);
                *reinterpret_cast<uint4*>(g_h + (n0 + r) * NF + c4 * 8) = vh;
            }
        }
    }
}

// ---------------------------------------------------------------------------
extern "C" void kernel_launch(void* const* d_in, const int* in_sizes, int n_in,
                              void* d_out, int out_size) {
    const float* x   = (const float*)d_in[0];
    const float* adj = (const float*)d_in[1];
    const float* W1  = (const float*)d_in[2];
    const float* W2  = (const float*)d_in[3];
    const float* W3  = (const float*)d_in[4];
    float* out = (float*)d_out;

    cudaFuncSetAttribute(upass_kernel,
                         cudaFuncAttributeMaxDynamicSharedMemorySize, 2 * U_STG128);
    cudaFuncSetAttribute(ppass_kernel<128, false>,
                         cudaFuncAttributeMaxDynamicSharedMemorySize, 40960);
    cudaFuncSetAttribute(ppass_kernel<32, true>,
                         cudaFuncAttributeMaxDynamicSharedMemorySize, 25600);

    init_kernel<<<440, 256>>>();
    conv_adj_kernel<<<800, 256>>>(adj);
    conv_x_kernel<<<25600, 256>>>(x);

    dim3 ugrid(3, NSLICE);

    upass_kernel<<<ugrid, 256, 2 * U_STG128>>>();
    mkM_kernel<128><<<150, 256>>>(W1);
    ppass_kernel<128, false><<<1563, 512, 40960>>>(nullptr);

    upass_kernel<<<ugrid, 256, 2 * U_STG128>>>();
    mkM_kernel<128><<<150, 256>>>(W2);
    ppass_kernel<128, false><<<1563, 512, 40960>>>(nullptr);

    upass_kernel<<<ugrid, 256, 2 * U_STG128>>>();
    mkM_kernel<32><<<150, 256>>>(W3);
    ppass_kernel<32, true><<<1563, 512, 25600>>>(out);
}

// round 17
// speedup vs baseline: 2.0190x; 1.0363x over previous
#include <cuda_runtime.h>
#include <cuda_fp16.h>
#include <cstdint>

#define NN 200000
#define PADK 200704
#define NA 300
#define NAP 320
#define NF 128
#define NC 32

#define KT 32
#define U_SLICE 1568          // 128 * 1568 = 200704 = PADK exactly
#define U_GRID 128

// ---------------- device scratch (row-padded to PADK) ----------------
__device__ __half g_adj[(size_t)PADK * NAP];
__device__ __half g_h[(size_t)PADK * NF];
__device__ float g_U[384 * NF];
__device__ __half g_MT[NF * NAP];
__device__ float g_rowsum[NN];
__device__ float g_colsum[384];

// ---------------- helpers ----------------
__device__ __forceinline__ uint32_t smem_u32(const void* p) {
    uint32_t a;
    asm("{ .reg .u64 t; cvta.to.shared.u64 t, %1; cvt.u32.u64 %0, t; }"
        : "=r"(a) : "l"(p));
    return a;
}
__device__ __forceinline__ void cpa(uint32_t dst, const void* src) {
    asm volatile("cp.async.cg.shared.global [%0], [%1], 16;"
                 :: "r"(dst), "l"(src) : "memory");
}
__device__ __forceinline__ void cpa_commit() {
    asm volatile("cp.async.commit_group;" ::: "memory");
}
template<int N> __device__ __forceinline__ void cpa_wait() {
    asm volatile("cp.async.wait_group %0;" :: "n"(N) : "memory");
}
__device__ __forceinline__ void ldm4(uint32_t* r, uint32_t a) {
    asm volatile("ldmatrix.sync.aligned.m8n8.x4.shared.b16 {%0,%1,%2,%3}, [%4];"
        : "=r"(r[0]), "=r"(r[1]), "=r"(r[2]), "=r"(r[3]) : "r"(a));
}
__device__ __forceinline__ void ldm4t(uint32_t* r, uint32_t a) {
    asm volatile("ldmatrix.sync.aligned.m8n8.x4.trans.shared.b16 {%0,%1,%2,%3}, [%4];"
        : "=r"(r[0]), "=r"(r[1]), "=r"(r[2]), "=r"(r[3]) : "r"(a));
}
__device__ __forceinline__ void mma16816(float* d, const uint32_t* a, const uint32_t* b) {
    asm volatile("mma.sync.aligned.m16n8k16.row.col.f32.f16.f16.f32 "
        "{%0,%1,%2,%3}, {%4,%5,%6,%7}, {%8,%9}, {%0,%1,%2,%3};"
        : "+f"(d[0]), "+f"(d[1]), "+f"(d[2]), "+f"(d[3])
        : "r"(a[0]), "r"(a[1]), "r"(a[2]), "r"(a[3]), "r"(b[0]), "r"(b[1]));
}

__device__ __forceinline__ uint32_t pack2h(float v0, float v1) {
    __half2 p = __halves2half2(__float2half(v0), __float2half(v1));
    return *reinterpret_cast<uint32_t*>(&p);
}

// ---------------------------------------------------------------------------
#define PADR (PADK - NN)
__global__ void init_kernel() {
    int i = blockIdx.x * blockDim.x + threadIdx.x;
    if (i < 384 * NF) g_U[i] = 0.f;
    if (i < 384) g_colsum[i] = 0.f;
    if (i < NF * NAP / 2)
        reinterpret_cast<uint32_t*>(g_MT)[i] = 0u;
    if (i < PADR * NAP / 2)
        reinterpret_cast<uint32_t*>(g_adj + (size_t)NN * NAP)[i] = 0u;
    if (i < PADR * NF / 2)
        reinterpret_cast<uint32_t*>(g_h + (size_t)NN * NF)[i] = 0u;
}

// ---------------------------------------------------------------------------
// adj -> fp16 (padded 320 cols) + rowsum + colsum in one pass
// ---------------------------------------------------------------------------
__device__ __forceinline__ void w4h(__half* ph, float4 v) {
    uint2 o;
    o.x = pack2h(v.x, v.y);
    o.y = pack2h(v.z, v.w);
    *reinterpret_cast<uint2*>(ph) = o;
}

#define CONV_ROWS 250
__global__ void __launch_bounds__(256) conv_adj_kernel(const float* __restrict__ adj) {
    const int tx = threadIdx.x & 31;
    const int ty = threadIdx.x >> 5;
    const int r0 = blockIdx.x * CONV_ROWS;
    const int r1 = min(r0 + CONV_ROWS, NN);

    float ca[12];
#pragma unroll
    for (int j = 0; j < 12; j++) ca[j] = 0.f;

    for (int r = r0 + ty; r < r1; r += 8) {
        const float4* row4 = (const float4*)(adj + (size_t)r * NA);
        float4 v0 = row4[tx];
        float4 v1 = row4[32 + tx];
        float4 v2 = (tx < 11) ? row4[64 + tx] : make_float4(0.f, 0.f, 0.f, 0.f);
        ca[0] += v0.x; ca[1] += v0.y; ca[2]  += v0.z; ca[3]  += v0.w;
        ca[4] += v1.x; ca[5] += v1.y; ca[6]  += v1.z; ca[7]  += v1.w;
        ca[8] += v2.x; ca[9] += v2.y; ca[10] += v2.z; ca[11] += v2.w;
        float rp = v0.x + v0.y + v0.z + v0.w
                 + v1.x + v1.y + v1.z + v1.w
                 + v2.x + v2.y + v2.z + v2.w;
#pragma unroll
        for (int o = 16; o > 0; o >>= 1)
            rp += __shfl_down_sync(0xffffffffu, rp, o);
        if (tx == 0) g_rowsum[r] = rp;

        __half* oh = g_adj + (size_t)r * NAP;
        w4h(oh + 4 * tx, v0);
        w4h(oh + 4 * (32 + tx), v1);
        if (tx < 16) w4h(oh + 4 * (64 + tx), v2);
    }

    __shared__ float sc[8][12][32];
#pragma unroll
    for (int j = 0; j < 12; j++) sc[ty][j][tx] = ca[j];
    __syncthreads();
    if (ty == 0) {
#pragma unroll
        for (int j = 0; j < 12; j++) {
            float s = 0.f;
#pragma unroll
            for (int t = 0; t < 8; t++) s += sc[t][j][tx];
            int col = (j >> 2) * 128 + tx * 4 + (j & 3);
            if (col < NA) atomicAdd(&g_colsum[col], s);
        }
    }
}

// ---------------------------------------------------------------------------
__global__ void conv_x_kernel(const float* __restrict__ x) {
    size_t i = (size_t)blockIdx.x * blockDim.x + threadIdx.x;
    if (i < (size_t)NN * NF / 4) {
        float4 v = ((const float4*)x)[i];
        uint2 o;
        o.x = pack2h(v.x, v.y);
        o.y = pack2h(v.z, v.w);
        *reinterpret_cast<uint2*>(g_h + 4 * i) = o;
    }
}

// ---------------------------------------------------------------------------
// upass: U[a][d] += sum_k adj[k][a]*h[k][d], computed as D[d][a] (m=d, n=a).
// ONE CTA per k-slice covers the FULL [128d x 320a] tile -> adj and h each
// read exactly once. 512 thr, 16 warps (4m x 4n), warp tile 32d x 80a.
// grid = 128 (one wave). 2-stage cp.async pipeline.
// ---------------------------------------------------------------------------
#define U_PA 272                 // h tile pitch (A operand, [32k][128d])
#define U_PB 656                 // adj tile pitch (B operand, [32k][320a]) 41*16
#define U_SAB (KT * U_PA)        // 8704
#define U_SBB (KT * U_PB)        // 20992
#define U_STG (U_SAB + U_SBB)    // 29696

__global__ void __launch_bounds__(512, 1) upass_kernel() {
    extern __shared__ char smem[];
    const uint32_t sb = smem_u32(smem);
    const int tid = threadIdx.x, wid = tid >> 5, L = tid & 31;
    const int warp_m = wid >> 2;      // d group (0..3)
    const int warp_n = wid & 3;       // a group (0..3)
    const size_t k0 = (size_t)blockIdx.x * U_SLICE;

    float acc[2][10][4];
#pragma unroll
    for (int i = 0; i < 2; i++)
#pragma unroll
        for (int j = 0; j < 10; j++)
#pragma unroll
            for (int q = 0; q < 4; q++) acc[i][j][q] = 0.f;

    auto load = [&](uint32_t base, size_t kt) {
        {   // A (h): 32 rows x 16 chunks = 512
            int row = tid >> 4, c = tid & 15;
            cpa(base + row * U_PA + c * 16, g_h + (kt + row) * NF + c * 8);
        }
#pragma unroll
        for (int it = 0; it < 3; it++) {   // B (adj): 32 rows x 40 chunks = 1280
            int idx = tid + it * 512;
            if (idx < 1280) {
                int row = idx / 40, c = idx % 40;
                cpa(base + U_SAB + row * U_PB + c * 16,
                    g_adj + (kt + row) * NAP + c * 8);
            }
        }
    };

    load(sb, k0);
    cpa_commit();

    const int T = U_SLICE / KT;   // 49
    for (int t = 0; t < T; t++) {
        cpa_wait<0>();
        __syncthreads();
        if (t + 1 < T) {
            load(sb + ((t + 1) & 1) * U_STG, k0 + (size_t)(t + 1) * KT);
            cpa_commit();
        }
        const uint32_t st = sb + (t & 1) * U_STG;
        const uint32_t Ah = st;           // h tile
        const uint32_t Bh = st + U_SAB;   // adj tile

#pragma unroll
        for (int ks = 0; ks < 2; ks++) {
            // A-operand trans map (m = d)
            const uint32_t aoff = (uint32_t)(ks * 16 + ((L >> 4) & 1) * 8 + (L & 7)) * U_PA
                                + ((L >> 3) & 1) * 16;
            uint32_t AF[2][4];
#pragma unroll
            for (int mb = 0; mb < 2; mb++) {
                uint32_t c2 = (uint32_t)(warp_m * 32 + mb * 16) * 2;
                ldm4t(AF[mb], Ah + aoff + c2);
            }
            // B-operand trans map (n = a)
            const uint32_t boff = (uint32_t)(ks * 16 + ((L >> 3) & 1) * 8 + (L & 7)) * U_PB
                                + ((L >> 4) & 1) * 16;
#pragma unroll
            for (int nb = 0; nb < 5; nb++) {
                uint32_t BH[4];
                uint32_t c2 = (uint32_t)(warp_n * 80 + nb * 16) * 2;
                ldm4t(BH, Bh + boff + c2);
#pragma unroll
                for (int mb = 0; mb < 2; mb++)
#pragma unroll
                    for (int jj = 0; jj < 2; jj++)
                        mma16816(acc[mb][nb * 2 + jj], AF[mb], &BH[jj * 2]);
            }
        }
    }

    // epilogue: D[d][a] -> atomicAdd g_U[a*NF + d]. No bounds needed:
    // a in [0,320) (U has 384 rows; adj pad cols are zero), d in [0,128).
#pragma unroll
    for (int mb = 0; mb < 2; mb++) {
        int d = warp_m * 32 + mb * 16 + (L >> 2);
#pragma unroll
        for (int j = 0; j < 10; j++) {
            int a = warp_n * 80 + j * 8 + (L & 3) * 2;
            atomicAdd(&g_U[a * NF + d],           acc[mb][j][0]);
            atomicAdd(&g_U[(a + 1) * NF + d],     acc[mb][j][1]);
            atomicAdd(&g_U[a * NF + d + 8],       acc[mb][j][2]);
            atomicAdd(&g_U[(a + 1) * NF + d + 8], acc[mb][j][3]);
        }
    }
}

// ---------------------------------------------------------------------------
// mkM: two anchors per CTA. M^T = (U@W)/clamp(colsum) fp16; zero U row.
// ---------------------------------------------------------------------------
template<int DOUT>
__global__ void mkM_kernel(const float* __restrict__ W) {
    __shared__ float u_s[2][NF];
    const int half = threadIdx.x >> 7;
    const int d = threadIdx.x & 127;
    const int a = blockIdx.x * 2 + half;
    u_s[half][d] = g_U[a * NF + d];
    __syncthreads();
    g_U[a * NF + d] = 0.f;
    if (d < DOUT) {
        float cinv = 1.f / fmaxf(g_colsum[a], 1e-12f);
        float acc = 0.f;
#pragma unroll 8
        for (int k = 0; k < NF; k++)
            acc += u_s[half][k] * W[k * DOUT + d];
        g_MT[d * NAP + a] = __float2half(acc * cinv);
    }
}

// ---------------------------------------------------------------------------
// ppass: C[n][d] = sum_a adj[n][a]*M[a][d]; 512 thr, 2-stage pipeline.
// Single fp16 operands, ONE MMA term. Coalesced smem epilogue.
// ---------------------------------------------------------------------------
template<int NOUT, bool FINAL>
__global__ void __launch_bounds__(512) ppass_kernel(float* __restrict__ out) {
    constexpr int WM = (NOUT == 128) ? 4 : 8;
    constexpr int WN = 16 / WM;
    constexpr int MT = 128 / WM;
    constexpr int NT = NOUT / WN;
    constexpr int MB = MT / 16;
    constexpr int N8 = NT / 8;
    constexpr int NBP = NT / 16;
    constexpr int P = 80;
    constexpr int SA = 128 * P;
    constexpr int SB = NOUT * P;
    constexpr int STG = SA + SB;
    constexpr int BCH = NOUT * 4;
    constexpr int EP = (NOUT == 128) ? 68 : 36;

    extern __shared__ char smem[];
    const uint32_t sb = smem_u32(smem);
    const int tid = threadIdx.x, wid = tid >> 5, L = tid & 31;
    const int warp_m = wid / WN, warp_n = wid % WN;
    const size_t n0 = (size_t)blockIdx.x * 128;

    float acc[MB][N8][4];
#pragma unroll
    for (int i = 0; i < MB; i++)
#pragma unroll
        for (int j = 0; j < N8; j++)
#pragma unroll
            for (int q = 0; q < 4; q++) acc[i][j][q] = 0.f;

    auto load_tile = [&](int t, int stage) {
        uint32_t base = sb + stage * STG;
        {
            int row = tid >> 2, c = tid & 3;
            const __half* src = g_adj + (n0 + row) * NAP + t * KT + c * 8;
            cpa(base + row * P + c * 16, src);
        }
        if (tid < BCH) {
            int row = tid >> 2, c = tid & 3;
            const __half* src = g_MT + row * NAP + t * KT + c * 8;
            cpa(base + SA + row * P + c * 16, src);
        }
    };

    load_tile(0, 0);
    cpa_commit();

    const int T = NAP / KT;  // 10
    for (int t = 0; t < T; t++) {
        cpa_wait<0>();
        __syncthreads();
        if (t + 1 < T) {
            load_tile(t + 1, (t + 1) & 1);
            cpa_commit();
        }
        const uint32_t st = sb + (t & 1) * STG;
        const uint32_t Ah = st;
        const uint32_t Bh = st + SA;

#pragma unroll
        for (int ks = 0; ks < 2; ks++) {
            const uint32_t aoff = (uint32_t)(((L >> 3) & 1) * 8 + (L & 7)) * P
                                + ks * 32 + ((L >> 4) & 1) * 16;
            uint32_t AF[MB][4];
#pragma unroll
            for (int mb = 0; mb < MB; mb++) {
                uint32_t ro = (uint32_t)(warp_m * MT + mb * 16) * P;
                ldm4(AF[mb], Ah + ro + aoff);
            }
            const uint32_t boff = (uint32_t)(((L >> 4) & 1) * 8 + (L & 7)) * P
                                + ks * 32 + ((L >> 3) & 1) * 16;
            uint32_t BF[NBP][4];
#pragma unroll
            for (int nb = 0; nb < NBP; nb++) {
                uint32_t ro = (uint32_t)(warp_n * NT + nb * 16) * P;
                ldm4(BF[nb], Bh + ro + boff);
            }
#pragma unroll
            for (int mb = 0; mb < MB; mb++)
#pragma unroll
                for (int j = 0; j < N8; j++)
                    mma16816(acc[mb][j], AF[mb], &BF[j >> 1][(j & 1) * 2]);
        }
    }

    // ---------------- epilogue: smem staging + coalesced stores ----------------
    __syncthreads();

    if (FINAL) {
        float* stg = reinterpret_cast<float*>(smem);
#pragma unroll
        for (int mb = 0; mb < MB; mb++) {
            int r0 = warp_m * MT + mb * 16 + (L >> 2);
            size_t gr0 = n0 + r0;
            float ri0 = (gr0 < NN) ? 1.f / fmaxf(g_rowsum[gr0], 1e-12f) : 0.f;
            float ri1 = (gr0 + 8 < NN) ? 1.f / fmaxf(g_rowsum[gr0 + 8], 1e-12f) : 0.f;
#pragma unroll
            for (int j = 0; j < N8; j++) {
                int d = warp_n * NT + j * 8 + (L & 3) * 2;
                stg[r0 * EP + d]           = acc[mb][j][0] * ri0;
                stg[r0 * EP + d + 1]       = acc[mb][j][1] * ri0;
                stg[(r0 + 8) * EP + d]     = acc[mb][j][2] * ri1;
                stg[(r0 + 8) * EP + d + 1] = acc[mb][j][3] * ri1;
            }
        }
        __syncthreads();
#pragma unroll
        for (int p = 0; p < 2; p++) {
            int idx = tid + p * 512;
            int r = idx >> 3, c4 = idx & 7;
            if (n0 + r < NN) {
                float4 v = *reinterpret_cast<float4*>(&stg[r * EP + c4 * 4]);
                *reinterpret_cast<float4*>(out + (n0 + r) * NC + c4 * 4) = v;
            }
        }
    } else {
        uint32_t* sh = reinterpret_cast<uint32_t*>(smem);
#pragma unroll
        for (int mb = 0; mb < MB; mb++) {
            int r0 = warp_m * MT + mb * 16 + (L >> 2);
            size_t gr0 = n0 + r0;
            float ri0 = (gr0 < NN) ? 1.f / fmaxf(g_rowsum[gr0], 1e-12f) : 0.f;
            float ri1 = (gr0 + 8 < NN) ? 1.f / fmaxf(g_rowsum[gr0 + 8], 1e-12f) : 0.f;
#pragma unroll
            for (int j = 0; j < N8; j++) {
                int dw = (warp_n * NT + j * 8) / 2 + (L & 3);
                sh[r0 * EP + dw] = pack2h(fmaxf(acc[mb][j][0] * ri0, 0.f),
                                          fmaxf(acc[mb][j][1] * ri0, 0.f));
                sh[(r0 + 8) * EP + dw] = pack2h(fmaxf(acc[mb][j][2] * ri1, 0.f),
                                                fmaxf(acc[mb][j][3] * ri1, 0.f));
            }
        }
        __syncthreads();
#pragma unroll
        for (int p = 0; p < 4; p++) {
            int idx = tid + p * 512;
            int r = idx >> 4, c4 = idx & 15;
            if (n0 + r < NN) {
                uint4 vh = *reinterpret_cast<uint4*>(&sh[r * EP + c4 * 4]);
                *reinterpret_cast<uint4*>(g_h + (n0 + r) * NF + c4 * 8) = vh;
            }
        }
    }
}

// ---------------------------------------------------------------------------
extern "C" void kernel_launch(void* const* d_in, const int* in_sizes, int n_in,
                              void* d_out, int out_size) {
    const float* x   = (const float*)d_in[0];
    const float* adj = (const float*)d_in[1];
    const float* W1  = (const float*)d_in[2];
    const float* W2  = (const float*)d_in[3];
    const float* W3  = (const float*)d_in[4];
    float* out = (float*)d_out;

    cudaFuncSetAttribute(upass_kernel,
                         cudaFuncAttributeMaxDynamicSharedMemorySize, 2 * U_STG);
    cudaFuncSetAttribute(ppass_kernel<128, false>,
                         cudaFuncAttributeMaxDynamicSharedMemorySize, 40960);
    cudaFuncSetAttribute(ppass_kernel<32, true>,
                         cudaFuncAttributeMaxDynamicSharedMemorySize, 25600);

    init_kernel<<<440, 256>>>();
    conv_adj_kernel<<<800, 256>>>(adj);
    conv_x_kernel<<<25600, 256>>>(x);

    upass_kernel<<<U_GRID, 512, 2 * U_STG>>>();
    mkM_kernel<128><<<150, 256>>>(W1);
    ppass_kernel<128, false><<<1563, 512, 40960>>>(nullptr);

    upass_kernel<<<U_GRID, 512, 2 * U_STG>>>();
    mkM_kernel<128><<<150, 256>>>(W2);
    ppass_kernel<128, false><<<1563, 512, 40960>>>(nullptr);

    upass_kernel<<<U_GRID, 512, 2 * U_STG>>>();
    mkM_kernel<32><<<150, 256>>>(W3);
    ppass_kernel<32, true><<<1563, 512, 25600>>>(out);
}